// round 1
// baseline (speedup 1.0000x reference)
#include <cuda_runtime.h>
#include <math.h>

#define BB 4
#define HH 8
#define SS 1024
#define DD 512
#define DKK 64

// Scratch (allocation-free rule: __device__ globals)
__device__ float g_v[BB*HH*SS*DKK];   // v projected, layout [b][h][k][dk]
__device__ float g_x[BB*SS*DD];       // attention output, layout [b][s][h*64+dk]

// C = A @ W^T + bias_vec. A:[4096,512] row-major, W:[512,512] row-major (W[n,k]).
// MODE 0: A = param, write permuted into g_v ([b][h][s][dk])
// MODE 1: A = g_x,   write directly to Cout[m*512+n]
template<int MODE>
__global__ void __launch_bounds__(256) gemm_nt(const float* __restrict__ Ain,
                                               const float* __restrict__ W,
                                               const float* __restrict__ bv,
                                               float* __restrict__ Cout)
{
    __shared__ float As[16][65];
    __shared__ float Bs[16][65];
    const int t  = threadIdx.x;
    const int tx = t & 15;
    const int ty = t >> 4;
    const int m0 = blockIdx.y * 64;
    const int n0 = blockIdx.x * 64;

    const float* __restrict__ A = (MODE == 0) ? Ain : g_x;

    float c[4][4];
    #pragma unroll
    for (int i = 0; i < 4; i++)
        #pragma unroll
        for (int j = 0; j < 4; j++) c[i][j] = 0.f;

    for (int k0 = 0; k0 < 512; k0 += 16) {
        #pragma unroll
        for (int r = 0; r < 4; r++) {
            int e  = t + 256 * r;
            int ml = e >> 4, kl = e & 15;
            As[kl][ml] = A[(m0 + ml) * 512 + k0 + kl];
            Bs[kl][ml] = W[(n0 + ml) * 512 + k0 + kl];
        }
        __syncthreads();
        #pragma unroll
        for (int kk = 0; kk < 16; kk++) {
            float a[4], b[4];
            #pragma unroll
            for (int i = 0; i < 4; i++) a[i] = As[kk][ty + i * 16];
            #pragma unroll
            for (int j = 0; j < 4; j++) b[j] = Bs[kk][tx + j * 16];
            #pragma unroll
            for (int i = 0; i < 4; i++)
                #pragma unroll
                for (int j = 0; j < 4; j++)
                    c[i][j] += a[i] * b[j];
        }
        __syncthreads();
    }

    #pragma unroll
    for (int i = 0; i < 4; i++) {
        int m = m0 + ty + i * 16;
        #pragma unroll
        for (int j = 0; j < 4; j++) {
            int n = n0 + tx + j * 16;
            float val = c[i][j] + bv[n];
            if (MODE == 0) {
                int b_ = m >> 10, s_ = m & 1023;
                int h_ = n >> 6,  d_ = n & 63;
                g_v[((((b_ * HH + h_) * SS) + s_) << 6) + d_] = val;
            } else {
                Cout[m * 512 + n] = val;
            }
        }
    }
}

// One block per (b, h, 64-row q-tile). Online softmax over 16 k-tiles of 64.
// Fuses the bias -> output copy into the bias load (bias is read exactly once).
__global__ void __launch_bounds__(256) attn_kernel(const float* __restrict__ bias,
                                                   const int*   __restrict__ mask,
                                                   float*       __restrict__ bias_out)
{
    __shared__ float w_s[64][65];
    __shared__ float v_s[64][65];
    __shared__ float mrow[64], lrow[64], fac[64];
    __shared__ float red[64][4];

    const int t  = threadIdx.x;
    const int tx = t & 15;
    const int ty = t >> 4;
    const int q0 = blockIdx.x * 64;
    const int h  = blockIdx.y;
    const int b  = blockIdx.z;

    const float* __restrict__ bias_base = bias     + (((size_t)(b * HH + h)) * SS + q0) * SS;
    float*       __restrict__ bout_base = bias_out + (((size_t)(b * HH + h)) * SS + q0) * SS;
    const int*   __restrict__ mask_base = mask     + ((size_t)(b * SS + q0)) * SS;
    const float* __restrict__ v_base    = g_v + ((size_t)(b * HH + h) * SS) * DKK;

    if (t < 64) { mrow[t] = -3.0e38f; lrow[t] = 0.f; }

    float acc[4][4];
    #pragma unroll
    for (int i = 0; i < 4; i++)
        #pragma unroll
        for (int j = 0; j < 4; j++) acc[i][j] = 0.f;

    const int rr = t >> 2;   // reduction row 0..63
    const int jj = t & 3;    // reduction lane 0..3

    for (int k0 = 0; k0 < SS; k0 += 64) {
        __syncthreads();  // protects smem reuse (and initial mrow/lrow init)

        // Load bias tile (+ copy to output), mask it, load v tile.
        #pragma unroll
        for (int r = 0; r < 16; r++) {
            int e  = t + 256 * r;
            int ql = e >> 6, kl = e & 63;
            float bvv = bias_base[(size_t)ql * SS + k0 + kl];
            bout_base[(size_t)ql * SS + k0 + kl] = bvv;
            int mv = mask_base[(size_t)ql * SS + k0 + kl];
            w_s[ql][kl] = mv ? bvv : -1e9f;
            v_s[ql][kl] = v_base[(k0 + ql) * DKK + kl];   // ql = k row, kl = dk
        }
        __syncthreads();

        // 1) row max (4 threads per row)
        float pm = -3.0e38f;
        #pragma unroll
        for (int i = 0; i < 16; i++) pm = fmaxf(pm, w_s[rr][jj * 16 + i]);
        red[rr][jj] = pm;
        __syncthreads();
        if (t < 64) {
            float nm = fmaxf(fmaxf(red[t][0], red[t][1]), fmaxf(red[t][2], red[t][3]));
            nm = fmaxf(nm, mrow[t]);
            fac[t] = __expf(mrow[t] - nm);
            mrow[t] = nm;
            lrow[t] *= fac[t];
        }
        __syncthreads();

        // 2) exp in place + partial row sum
        float ps = 0.f;
        float mv_ = mrow[rr];
        #pragma unroll
        for (int i = 0; i < 16; i++) {
            float p = __expf(w_s[rr][jj * 16 + i] - mv_);
            w_s[rr][jj * 16 + i] = p;
            ps += p;
        }
        red[rr][jj] = ps;
        __syncthreads();
        if (t < 64) lrow[t] += red[t][0] + red[t][1] + red[t][2] + red[t][3];

        // rescale accumulators by per-row factor
        #pragma unroll
        for (int i = 0; i < 4; i++) {
            float f = fac[ty + i * 16];
            #pragma unroll
            for (int j = 0; j < 4; j++) acc[i][j] *= f;
        }

        // 3) PV accumulate: 64x64 tile, 4x4 microtile per thread
        #pragma unroll
        for (int kk = 0; kk < 64; kk++) {
            float bv4[4];
            #pragma unroll
            for (int j = 0; j < 4; j++) bv4[j] = v_s[kk][tx + j * 16];
            #pragma unroll
            for (int i = 0; i < 4; i++) {
                float p = w_s[ty + i * 16][kk];
                #pragma unroll
                for (int j = 0; j < 4; j++) acc[i][j] += p * bv4[j];
            }
        }
    }
    __syncthreads();  // lrow final

    #pragma unroll
    for (int i = 0; i < 4; i++) {
        int q = q0 + ty + i * 16;
        float inv = 1.f / lrow[ty + i * 16];
        #pragma unroll
        for (int j = 0; j < 4; j++) {
            int dk = tx + j * 16;
            g_x[((size_t)(b * SS + q)) * DD + h * DKK + dk] = acc[i][j] * inv;
        }
    }
}

extern "C" void kernel_launch(void* const* d_in, const int* in_sizes, int n_in,
                              void* d_out, int out_size)
{
    // metadata order: query, key, value, bias, mask, W_v, b_v, W_o, b_o
    const float* value = (const float*)d_in[2];
    const float* bias  = (const float*)d_in[3];
    const int*   mask  = (const int*)  d_in[4];
    const float* W_v   = (const float*)d_in[5];
    const float* b_v   = (const float*)d_in[6];
    const float* W_o   = (const float*)d_in[7];
    const float* b_o   = (const float*)d_in[8];

    float* out      = (float*)d_out;                 // [B,S,D] = 2,097,152 floats
    float* bias_out = out + (size_t)BB * SS * DD;    // [B,H,S,S] = 33,554,432 floats

    // 1) V projection -> g_v [b][h][s][dk]
    gemm_nt<0><<<dim3(8, 64), 256>>>(value, W_v, b_v, nullptr);

    // 2) masked softmax(bias) @ v  (+ fused bias copy) -> g_x [b][s][d]
    attn_kernel<<<dim3(SS / 64, HH, BB), 256>>>(bias, mask, bias_out);

    // 3) O projection -> out
    gemm_nt<1><<<dim3(8, 64), 256>>>(nullptr, W_o, b_o, out);
}

// round 3
// speedup vs baseline: 1.3375x; 1.3375x over previous
#include <cuda_runtime.h>
#include <cuda_bf16.h>
#include <stdint.h>
#include <math.h>

#define BB 4
#define HH 8
#define SS 1024
#define DD 512
#define DKK 64

// Scratch (allocation-free rule: __device__ globals)
__device__ float g_v[BB*HH*SS*DKK];   // v projected, layout [b][h][k][dk]
__device__ float g_x[BB*SS*DD];       // attention output, layout [b][s][h*64+dk]

// bf16 hi/lo split helpers
__device__ __forceinline__ uint32_t pack_bf(__nv_bfloat16 a, __nv_bfloat16 b) {
    return (uint32_t)__bfloat16_as_ushort(a) | ((uint32_t)__bfloat16_as_ushort(b) << 16);
}
__device__ __forceinline__ void split1(float x, __nv_bfloat16& h, __nv_bfloat16& l) {
    h = __float2bfloat16(x);
    l = __float2bfloat16(x - __bfloat162float(h));
}

__device__ __forceinline__ void mma16816(float* d, const uint32_t* a, const uint32_t* b) {
    asm volatile(
        "mma.sync.aligned.m16n8k16.row.col.f32.bf16.bf16.f32 "
        "{%0,%1,%2,%3}, {%4,%5,%6,%7}, {%8,%9}, {%0,%1,%2,%3};"
        : "+f"(d[0]), "+f"(d[1]), "+f"(d[2]), "+f"(d[3])
        : "r"(a[0]), "r"(a[1]), "r"(a[2]), "r"(a[3]), "r"(b[0]), "r"(b[1]));
}

// ================= tensor-core GEMM via mma.sync (HMMA, bf16 hi/lo split) ==========
// C = A @ W^T + bv. A:[4096,512], W:[512,512] row-major.
// CTA tile 128x128, 8 warps in 4(m) x 2(n), warp tile 32x64, K chunk 32.
// 3 passes hi@hi + hi@lo + lo@hi accumulate into the same fp32 accumulators.
// MODE 0: A = param, scatter into g_v [b][h][s][dk]. MODE 1: A = g_x, C -> Cout.
#define AST 40   // smem row stride (bf16 elems): 20 words -> conflict-free frag loads

template<int MODE>
__global__ void __launch_bounds__(256) gemm_mma(const float* __restrict__ Ain,
                                                const float* __restrict__ W,
                                                const float* __restrict__ bv,
                                                float* __restrict__ Cout)
{
    __shared__ __align__(16) __nv_bfloat16 Ahi[128][AST];
    __shared__ __align__(16) __nv_bfloat16 Alo[128][AST];
    __shared__ __align__(16) __nv_bfloat16 Bhi[128][AST];
    __shared__ __align__(16) __nv_bfloat16 Blo[128][AST];

    const int t = threadIdx.x, wid = t >> 5, lane = t & 31;
    const int wm = wid & 3, wn = wid >> 2;           // warp tile: rows wm*32, cols wn*64
    const int n0 = blockIdx.x * 128, m0 = blockIdx.y * 128;
    const int gr = lane >> 2, gc = (lane & 3) * 2;   // fragment row/col within tile
    const float* __restrict__ A = (MODE == 0) ? Ain : g_x;

    float acc[2][8][4];
    #pragma unroll
    for (int i = 0; i < 2; i++)
        #pragma unroll
        for (int j = 0; j < 8; j++)
            #pragma unroll
            for (int q = 0; q < 4; q++) acc[i][j][q] = 0.f;

    for (int k0 = 0; k0 < 512; k0 += 32) {
        // ---- load 128x32 fp32 of A and W, split to bf16 hi/lo in smem ----
        #pragma unroll
        for (int it = 0; it < 4; it++) {
            int g = t + it * 256;            // 1024 float4 slots: row = g>>3, grp = g&7
            int row = g >> 3, grp = g & 7;
            {
                float4 v4 = *(const float4*)&A[(size_t)(m0 + row) * 512 + k0 + grp * 4];
                __nv_bfloat16 h0,h1,h2,h3,l0,l1,l2,l3;
                split1(v4.x,h0,l0); split1(v4.y,h1,l1); split1(v4.z,h2,l2); split1(v4.w,h3,l3);
                *(uint2*)&Ahi[row][grp*4] = make_uint2(pack_bf(h0,h1), pack_bf(h2,h3));
                *(uint2*)&Alo[row][grp*4] = make_uint2(pack_bf(l0,l1), pack_bf(l2,l3));
            }
            {
                float4 v4 = *(const float4*)&W[(size_t)(n0 + row) * 512 + k0 + grp * 4];
                __nv_bfloat16 h0,h1,h2,h3,l0,l1,l2,l3;
                split1(v4.x,h0,l0); split1(v4.y,h1,l1); split1(v4.z,h2,l2); split1(v4.w,h3,l3);
                *(uint2*)&Bhi[row][grp*4] = make_uint2(pack_bf(h0,h1), pack_bf(h2,h3));
                *(uint2*)&Blo[row][grp*4] = make_uint2(pack_bf(l0,l1), pack_bf(l2,l3));
            }
        }
        __syncthreads();

        // ---- compute: two k16 steps ----
        #pragma unroll
        for (int kk = 0; kk < 32; kk += 16) {
            uint32_t ah[2][4], al[2][4], bh[8][2], bl[8][2];
            #pragma unroll
            for (int mi = 0; mi < 2; mi++) {
                int r = wm * 32 + mi * 16 + gr;
                ah[mi][0] = *(const uint32_t*)&Ahi[r    ][kk + gc];
                ah[mi][1] = *(const uint32_t*)&Ahi[r + 8][kk + gc];
                ah[mi][2] = *(const uint32_t*)&Ahi[r    ][kk + gc + 8];
                ah[mi][3] = *(const uint32_t*)&Ahi[r + 8][kk + gc + 8];
            }
            #pragma unroll
            for (int nj = 0; nj < 8; nj++) {
                int r = wn * 64 + nj * 8 + gr;
                bh[nj][0] = *(const uint32_t*)&Bhi[r][kk + gc];
                bh[nj][1] = *(const uint32_t*)&Bhi[r][kk + gc + 8];
            }
            #pragma unroll
            for (int mi = 0; mi < 2; mi++)
                #pragma unroll
                for (int nj = 0; nj < 8; nj++) mma16816(acc[mi][nj], ah[mi], bh[nj]);

            #pragma unroll
            for (int nj = 0; nj < 8; nj++) {
                int r = wn * 64 + nj * 8 + gr;
                bl[nj][0] = *(const uint32_t*)&Blo[r][kk + gc];
                bl[nj][1] = *(const uint32_t*)&Blo[r][kk + gc + 8];
            }
            #pragma unroll
            for (int mi = 0; mi < 2; mi++)
                #pragma unroll
                for (int nj = 0; nj < 8; nj++) mma16816(acc[mi][nj], ah[mi], bl[nj]);

            #pragma unroll
            for (int mi = 0; mi < 2; mi++) {
                int r = wm * 32 + mi * 16 + gr;
                al[mi][0] = *(const uint32_t*)&Alo[r    ][kk + gc];
                al[mi][1] = *(const uint32_t*)&Alo[r + 8][kk + gc];
                al[mi][2] = *(const uint32_t*)&Alo[r    ][kk + gc + 8];
                al[mi][3] = *(const uint32_t*)&Alo[r + 8][kk + gc + 8];
            }
            #pragma unroll
            for (int mi = 0; mi < 2; mi++)
                #pragma unroll
                for (int nj = 0; nj < 8; nj++) mma16816(acc[mi][nj], al[mi], bh[nj]);
        }
        __syncthreads();
    }

    // ---- epilogue: add bias vector, write out ----
    #pragma unroll
    for (int mi = 0; mi < 2; mi++) {
        int r0 = m0 + wm * 32 + mi * 16 + gr;
        #pragma unroll
        for (int nj = 0; nj < 8; nj++) {
            int n = n0 + wn * 64 + nj * 8 + gc;
            float v00 = acc[mi][nj][0] + bv[n];
            float v01 = acc[mi][nj][1] + bv[n + 1];
            float v10 = acc[mi][nj][2] + bv[n];
            float v11 = acc[mi][nj][3] + bv[n + 1];
            if (MODE == 0) {
                int h_ = n >> 6, d_ = n & 63;
                int b0_ = r0 >> 10, s0_ = r0 & 1023;
                int b1_ = (r0 + 8) >> 10, s1_ = (r0 + 8) & 1023;
                float* p0 = &g_v[((((b0_ * HH + h_) * SS) + s0_) << 6) + d_];
                float* p1 = &g_v[((((b1_ * HH + h_) * SS) + s1_) << 6) + d_];
                p0[0] = v00; p0[1] = v01;
                p1[0] = v10; p1[1] = v11;
            } else {
                Cout[(size_t)r0 * 512 + n]           = v00;
                Cout[(size_t)r0 * 512 + n + 1]       = v01;
                Cout[(size_t)(r0 + 8) * 512 + n]     = v10;
                Cout[(size_t)(r0 + 8) * 512 + n + 1] = v11;
            }
        }
    }
}

// ======================= attention (unchanged, known-correct) =======================
__global__ void __launch_bounds__(256) attn_kernel(const float* __restrict__ bias,
                                                   const int*   __restrict__ mask,
                                                   float*       __restrict__ bias_out)
{
    __shared__ float w_s[64][65];
    __shared__ float v_s[64][65];
    __shared__ float mrow[64], lrow[64], fac[64];
    __shared__ float red[64][4];

    const int t  = threadIdx.x;
    const int tx = t & 15;
    const int ty = t >> 4;
    const int q0 = blockIdx.x * 64;
    const int h  = blockIdx.y;
    const int b  = blockIdx.z;

    const float* __restrict__ bias_base = bias     + (((size_t)(b * HH + h)) * SS + q0) * SS;
    float*       __restrict__ bout_base = bias_out + (((size_t)(b * HH + h)) * SS + q0) * SS;
    const int*   __restrict__ mask_base = mask     + ((size_t)(b * SS + q0)) * SS;
    const float* __restrict__ v_base    = g_v + ((size_t)(b * HH + h) * SS) * DKK;

    if (t < 64) { mrow[t] = -3.0e38f; lrow[t] = 0.f; }

    float acc[4][4];
    #pragma unroll
    for (int i = 0; i < 4; i++)
        #pragma unroll
        for (int j = 0; j < 4; j++) acc[i][j] = 0.f;

    const int rr = t >> 2;
    const int jj = t & 3;

    for (int k0 = 0; k0 < SS; k0 += 64) {
        __syncthreads();

        #pragma unroll
        for (int r = 0; r < 16; r++) {
            int e  = t + 256 * r;
            int ql = e >> 6, kl = e & 63;
            float bvv = bias_base[(size_t)ql * SS + k0 + kl];
            bout_base[(size_t)ql * SS + k0 + kl] = bvv;
            int mv = mask_base[(size_t)ql * SS + k0 + kl];
            w_s[ql][kl] = mv ? bvv : -1e9f;
            v_s[ql][kl] = v_base[(k0 + ql) * DKK + kl];
        }
        __syncthreads();

        float pm = -3.0e38f;
        #pragma unroll
        for (int i = 0; i < 16; i++) pm = fmaxf(pm, w_s[rr][jj * 16 + i]);
        red[rr][jj] = pm;
        __syncthreads();
        if (t < 64) {
            float nm = fmaxf(fmaxf(red[t][0], red[t][1]), fmaxf(red[t][2], red[t][3]));
            nm = fmaxf(nm, mrow[t]);
            fac[t] = __expf(mrow[t] - nm);
            mrow[t] = nm;
            lrow[t] *= fac[t];
        }
        __syncthreads();

        float ps = 0.f;
        float mv_ = mrow[rr];
        #pragma unroll
        for (int i = 0; i < 16; i++) {
            float p = __expf(w_s[rr][jj * 16 + i] - mv_);
            w_s[rr][jj * 16 + i] = p;
            ps += p;
        }
        red[rr][jj] = ps;
        __syncthreads();
        if (t < 64) lrow[t] += red[t][0] + red[t][1] + red[t][2] + red[t][3];

        #pragma unroll
        for (int i = 0; i < 4; i++) {
            float f = fac[ty + i * 16];
            #pragma unroll
            for (int j = 0; j < 4; j++) acc[i][j] *= f;
        }

        #pragma unroll
        for (int kk = 0; kk < 64; kk++) {
            float bv4[4];
            #pragma unroll
            for (int j = 0; j < 4; j++) bv4[j] = v_s[kk][tx + j * 16];
            #pragma unroll
            for (int i = 0; i < 4; i++) {
                float p = w_s[ty + i * 16][kk];
                #pragma unroll
                for (int j = 0; j < 4; j++) acc[i][j] += p * bv4[j];
            }
        }
    }
    __syncthreads();

    #pragma unroll
    for (int i = 0; i < 4; i++) {
        int q = q0 + ty + i * 16;
        float inv = 1.f / lrow[ty + i * 16];
        #pragma unroll
        for (int j = 0; j < 4; j++) {
            int dk = tx + j * 16;
            g_x[((size_t)(b * SS + q)) * DD + h * DKK + dk] = acc[i][j] * inv;
        }
    }
}

extern "C" void kernel_launch(void* const* d_in, const int* in_sizes, int n_in,
                              void* d_out, int out_size)
{
    // metadata order: query, key, value, bias, mask, W_v, b_v, W_o, b_o
    const float* value = (const float*)d_in[2];
    const float* bias  = (const float*)d_in[3];
    const int*   mask  = (const int*)  d_in[4];
    const float* W_v   = (const float*)d_in[5];
    const float* b_v   = (const float*)d_in[6];
    const float* W_o   = (const float*)d_in[7];
    const float* b_o   = (const float*)d_in[8];

    float* out      = (float*)d_out;                 // [B,S,D]
    float* bias_out = out + (size_t)BB * SS * DD;    // [B,H,S,S]

    // 1) V projection -> g_v [b][h][s][dk]   (HMMA, bf16 hi/lo split)
    gemm_mma<0><<<dim3(4, 32), 256>>>(value, W_v, b_v, nullptr);

    // 2) masked softmax(bias) @ v  (+ fused bias copy) -> g_x [b][s][d]
    attn_kernel<<<dim3(SS / 64, HH, BB), 256>>>(bias, mask, bias_out);

    // 3) O projection -> out   (HMMA)
    gemm_mma<1><<<dim3(4, 32), 256>>>(nullptr, W_o, b_o, out);
}

// round 4
// speedup vs baseline: 1.4437x; 1.0795x over previous
#include <cuda_runtime.h>
#include <cuda_bf16.h>
#include <stdint.h>
#include <math.h>

#define BB 4
#define HH 8
#define SS 1024
#define DD 512
#define DKK 64

// Scratch (allocation-free rule: __device__ globals)
// V projected, pre-split bf16 hi/lo, TRANSPOSED layout [b][h][dk][s]
__device__ __nv_bfloat16 g_vh[BB*HH*DKK*SS];
__device__ __nv_bfloat16 g_vl[BB*HH*DKK*SS];
__device__ float g_x[BB*SS*DD];       // attention output, layout [b][s][h*64+dk]

// bf16 hi/lo split helpers
__device__ __forceinline__ uint32_t pack_bf(__nv_bfloat16 a, __nv_bfloat16 b) {
    return (uint32_t)__bfloat16_as_ushort(a) | ((uint32_t)__bfloat16_as_ushort(b) << 16);
}
__device__ __forceinline__ void split1(float x, __nv_bfloat16& h, __nv_bfloat16& l) {
    h = __float2bfloat16(x);
    l = __float2bfloat16(x - __bfloat162float(h));
}

__device__ __forceinline__ void mma16816(float* d, const uint32_t* a, const uint32_t* b) {
    asm volatile(
        "mma.sync.aligned.m16n8k16.row.col.f32.bf16.bf16.f32 "
        "{%0,%1,%2,%3}, {%4,%5,%6,%7}, {%8,%9}, {%0,%1,%2,%3};"
        : "+f"(d[0]), "+f"(d[1]), "+f"(d[2]), "+f"(d[3])
        : "r"(a[0]), "r"(a[1]), "r"(a[2]), "r"(a[3]), "r"(b[0]), "r"(b[1]));
}

// ================= tensor-core GEMM via mma.sync (HMMA, bf16 hi/lo split) ==========
// C = A @ W^T + bv. A:[4096,512], W:[512,512] row-major.
// CTA tile 128x128, 8 warps in 4(m) x 2(n), warp tile 32x64, K chunk 32.
// MODE 0: A = param, write bf16 hi/lo split V transposed into g_vh/g_vl [b][h][dk][s].
// MODE 1: A = g_x, C -> Cout fp32.
#define AST 40   // smem row stride (bf16 elems): 20 words -> conflict-free frag loads

template<int MODE>
__global__ void __launch_bounds__(256) gemm_mma(const float* __restrict__ Ain,
                                                const float* __restrict__ W,
                                                const float* __restrict__ bv,
                                                float* __restrict__ Cout)
{
    __shared__ __align__(16) __nv_bfloat16 Ahi[128][AST];
    __shared__ __align__(16) __nv_bfloat16 Alo[128][AST];
    __shared__ __align__(16) __nv_bfloat16 Bhi[128][AST];
    __shared__ __align__(16) __nv_bfloat16 Blo[128][AST];

    const int t = threadIdx.x, wid = t >> 5, lane = t & 31;
    const int wm = wid & 3, wn = wid >> 2;
    const int n0 = blockIdx.x * 128, m0 = blockIdx.y * 128;
    const int gr = lane >> 2, gc = (lane & 3) * 2;
    const float* __restrict__ A = (MODE == 0) ? Ain : g_x;

    float acc[2][8][4];
    #pragma unroll
    for (int i = 0; i < 2; i++)
        #pragma unroll
        for (int j = 0; j < 8; j++)
            #pragma unroll
            for (int q = 0; q < 4; q++) acc[i][j][q] = 0.f;

    for (int k0 = 0; k0 < 512; k0 += 32) {
        #pragma unroll
        for (int it = 0; it < 4; it++) {
            int g = t + it * 256;
            int row = g >> 3, grp = g & 7;
            {
                float4 v4 = *(const float4*)&A[(size_t)(m0 + row) * 512 + k0 + grp * 4];
                __nv_bfloat16 h0,h1,h2,h3,l0,l1,l2,l3;
                split1(v4.x,h0,l0); split1(v4.y,h1,l1); split1(v4.z,h2,l2); split1(v4.w,h3,l3);
                *(uint2*)&Ahi[row][grp*4] = make_uint2(pack_bf(h0,h1), pack_bf(h2,h3));
                *(uint2*)&Alo[row][grp*4] = make_uint2(pack_bf(l0,l1), pack_bf(l2,l3));
            }
            {
                float4 v4 = *(const float4*)&W[(size_t)(n0 + row) * 512 + k0 + grp * 4];
                __nv_bfloat16 h0,h1,h2,h3,l0,l1,l2,l3;
                split1(v4.x,h0,l0); split1(v4.y,h1,l1); split1(v4.z,h2,l2); split1(v4.w,h3,l3);
                *(uint2*)&Bhi[row][grp*4] = make_uint2(pack_bf(h0,h1), pack_bf(h2,h3));
                *(uint2*)&Blo[row][grp*4] = make_uint2(pack_bf(l0,l1), pack_bf(l2,l3));
            }
        }
        __syncthreads();

        #pragma unroll
        for (int kk = 0; kk < 32; kk += 16) {
            uint32_t ah[2][4], al[2][4], bh[8][2], bl[8][2];
            #pragma unroll
            for (int mi = 0; mi < 2; mi++) {
                int r = wm * 32 + mi * 16 + gr;
                ah[mi][0] = *(const uint32_t*)&Ahi[r    ][kk + gc];
                ah[mi][1] = *(const uint32_t*)&Ahi[r + 8][kk + gc];
                ah[mi][2] = *(const uint32_t*)&Ahi[r    ][kk + gc + 8];
                ah[mi][3] = *(const uint32_t*)&Ahi[r + 8][kk + gc + 8];
            }
            #pragma unroll
            for (int nj = 0; nj < 8; nj++) {
                int r = wn * 64 + nj * 8 + gr;
                bh[nj][0] = *(const uint32_t*)&Bhi[r][kk + gc];
                bh[nj][1] = *(const uint32_t*)&Bhi[r][kk + gc + 8];
            }
            #pragma unroll
            for (int mi = 0; mi < 2; mi++)
                #pragma unroll
                for (int nj = 0; nj < 8; nj++) mma16816(acc[mi][nj], ah[mi], bh[nj]);

            #pragma unroll
            for (int nj = 0; nj < 8; nj++) {
                int r = wn * 64 + nj * 8 + gr;
                bl[nj][0] = *(const uint32_t*)&Blo[r][kk + gc];
                bl[nj][1] = *(const uint32_t*)&Blo[r][kk + gc + 8];
            }
            #pragma unroll
            for (int mi = 0; mi < 2; mi++)
                #pragma unroll
                for (int nj = 0; nj < 8; nj++) mma16816(acc[mi][nj], ah[mi], bl[nj]);

            #pragma unroll
            for (int mi = 0; mi < 2; mi++) {
                int r = wm * 32 + mi * 16 + gr;
                al[mi][0] = *(const uint32_t*)&Alo[r    ][kk + gc];
                al[mi][1] = *(const uint32_t*)&Alo[r + 8][kk + gc];
                al[mi][2] = *(const uint32_t*)&Alo[r    ][kk + gc + 8];
                al[mi][3] = *(const uint32_t*)&Alo[r + 8][kk + gc + 8];
            }
            #pragma unroll
            for (int mi = 0; mi < 2; mi++)
                #pragma unroll
                for (int nj = 0; nj < 8; nj++) mma16816(acc[mi][nj], al[mi], bh[nj]);
        }
        __syncthreads();
    }

    // ---- epilogue ----
    #pragma unroll
    for (int mi = 0; mi < 2; mi++) {
        int r0 = m0 + wm * 32 + mi * 16 + gr;
        #pragma unroll
        for (int nj = 0; nj < 8; nj++) {
            int n = n0 + wn * 64 + nj * 8 + gc;
            float v00 = acc[mi][nj][0] + bv[n];
            float v01 = acc[mi][nj][1] + bv[n + 1];
            float v10 = acc[mi][nj][2] + bv[n];
            float v11 = acc[mi][nj][3] + bv[n + 1];
            if (MODE == 0) {
                // split + store transposed: [b][h][dk][s]
                int h_ = n >> 6, d_ = n & 63;
                int b0_ = r0 >> 10, s0_ = r0 & 1023;
                int b1_ = (r0 + 8) >> 10, s1_ = (r0 + 8) & 1023;
                size_t p00 = (((size_t)(b0_ * HH + h_) * DKK) + d_) * SS + s0_;
                size_t p01 = (((size_t)(b0_ * HH + h_) * DKK) + d_ + 1) * SS + s0_;
                size_t p10 = (((size_t)(b1_ * HH + h_) * DKK) + d_) * SS + s1_;
                size_t p11 = (((size_t)(b1_ * HH + h_) * DKK) + d_ + 1) * SS + s1_;
                __nv_bfloat16 hh, ll;
                split1(v00, hh, ll); g_vh[p00] = hh; g_vl[p00] = ll;
                split1(v01, hh, ll); g_vh[p01] = hh; g_vl[p01] = ll;
                split1(v10, hh, ll); g_vh[p10] = hh; g_vl[p10] = ll;
                split1(v11, hh, ll); g_vh[p11] = hh; g_vl[p11] = ll;
            } else {
                Cout[(size_t)r0 * 512 + n]           = v00;
                Cout[(size_t)r0 * 512 + n + 1]       = v01;
                Cout[(size_t)(r0 + 8) * 512 + n]     = v10;
                Cout[(size_t)(r0 + 8) * 512 + n + 1] = v11;
            }
        }
    }
}

// ======================= attention v2: HMMA PV, no-max softmax =======================
// Grid (8,8,4): per block 128 q rows. K streamed in chunks of 64.
// P = exp(bias) masked (softmax shift-invariance: bias ~N(0,1), no max needed),
// split to bf16 hi/lo; PV via 3-pass m16n8k16; normalize by rowsum in epilogue.
#define PST 72   // smem stride (bf16): 36 words -> conflict-free frag loads
#define ATTN_SMEM ((128 * PST * 2 + 64 * PST * 2) * 2 + 512 + 16)

__global__ void __launch_bounds__(256) attn2(const float* __restrict__ bias,
                                             const int*   __restrict__ mask,
                                             float*       __restrict__ bias_out)
{
    extern __shared__ __align__(16) char smem[];
    typedef __nv_bfloat16 bf;
    bf (*Ph)[PST] = (bf(*)[PST])(smem);
    bf (*Pl)[PST] = (bf(*)[PST])(smem + 128 * PST * 2);
    bf (*Vh)[PST] = (bf(*)[PST])(smem + 2 * 128 * PST * 2);
    bf (*Vl)[PST] = (bf(*)[PST])(smem + 2 * 128 * PST * 2 + 64 * PST * 2);
    float* lsum   = (float*)(smem + 2 * 128 * PST * 2 + 2 * 64 * PST * 2);

    const int t = threadIdx.x, wid = t >> 5, lane = t & 31;
    const int gr = lane >> 2, gc = (lane & 3) * 2;
    const int q0 = blockIdx.x * 128;
    const int h  = blockIdx.y;
    const int b  = blockIdx.z;

    const float* __restrict__ bias_base = bias     + (((size_t)(b * HH + h)) * SS + q0) * SS;
    float*       __restrict__ bout_base = bias_out + (((size_t)(b * HH + h)) * SS + q0) * SS;
    const int*   __restrict__ mask_base = mask     + ((size_t)(b * SS + q0)) * SS;
    const bf*    __restrict__ vh_base   = g_vh + ((size_t)(b * HH + h) * DKK) * SS;
    const bf*    __restrict__ vl_base   = g_vl + ((size_t)(b * HH + h) * DKK) * SS;

    const int prow = t >> 1;           // 0..127 : row owned for P generation
    const int pc0  = (t & 1) * 32;     // column half

    float rsum = 0.f;
    float acc[8][4];
    #pragma unroll
    for (int j = 0; j < 8; j++)
        #pragma unroll
        for (int q = 0; q < 4; q++) acc[j][q] = 0.f;

    for (int k0 = 0; k0 < SS; k0 += 64) {
        __syncthreads();   // previous chunk's MMA done before smem overwrite

        // ---- P tile: 128 x 64 ----
        const float* bp = bias_base + (size_t)prow * SS + k0 + pc0;
        float*       bo = bout_base + (size_t)prow * SS + k0 + pc0;
        const int*   mp = mask_base + (size_t)prow * SS + k0 + pc0;
        #pragma unroll
        for (int j = 0; j < 8; j++) {
            float4 b4 = *(const float4*)(bp + j * 4);
            *(float4*)(bo + j * 4) = b4;
            int4 m4 = *(const int4*)(mp + j * 4);
            float p0 = m4.x ? __expf(b4.x) : 0.f;
            float p1 = m4.y ? __expf(b4.y) : 0.f;
            float p2 = m4.z ? __expf(b4.z) : 0.f;
            float p3 = m4.w ? __expf(b4.w) : 0.f;
            rsum += (p0 + p1) + (p2 + p3);
            __nv_bfloat16 h0,h1,h2,h3,l0,l1,l2,l3;
            split1(p0,h0,l0); split1(p1,h1,l1); split1(p2,h2,l2); split1(p3,h3,l3);
            *(uint2*)&Ph[prow][pc0 + j * 4] = make_uint2(pack_bf(h0,h1), pack_bf(h2,h3));
            *(uint2*)&Pl[prow][pc0 + j * 4] = make_uint2(pack_bf(l0,l1), pack_bf(l2,l3));
        }

        // ---- V tile: 64 (dk) x 64 (k), from transposed pre-split global ----
        #pragma unroll
        for (int it = 0; it < 4; it++) {
            int g = t + it * 256;          // 1024 uint2 slots
            int row = g >> 4, c4 = (g & 15) * 4;
            *(uint2*)&Vh[row][c4] = *(const uint2*)&vh_base[(size_t)row * SS + k0 + c4];
            *(uint2*)&Vl[row][c4] = *(const uint2*)&vl_base[(size_t)row * SS + k0 + c4];
        }
        __syncthreads();

        // ---- MMA: warp tile m16 (rows wid*16) x n64, 4 k16 steps ----
        const int qb = wid * 16;
        #pragma unroll
        for (int kk = 0; kk < 64; kk += 16) {
            uint32_t ah[4], al[4], bh[8][2], bl[8][2];
            ah[0] = *(const uint32_t*)&Ph[qb + gr    ][kk + gc];
            ah[1] = *(const uint32_t*)&Ph[qb + gr + 8][kk + gc];
            ah[2] = *(const uint32_t*)&Ph[qb + gr    ][kk + gc + 8];
            ah[3] = *(const uint32_t*)&Ph[qb + gr + 8][kk + gc + 8];
            #pragma unroll
            for (int nj = 0; nj < 8; nj++) {
                int r = nj * 8 + gr;
                bh[nj][0] = *(const uint32_t*)&Vh[r][kk + gc];
                bh[nj][1] = *(const uint32_t*)&Vh[r][kk + gc + 8];
            }
            #pragma unroll
            for (int nj = 0; nj < 8; nj++) mma16816(acc[nj], ah, bh[nj]);

            #pragma unroll
            for (int nj = 0; nj < 8; nj++) {
                int r = nj * 8 + gr;
                bl[nj][0] = *(const uint32_t*)&Vl[r][kk + gc];
                bl[nj][1] = *(const uint32_t*)&Vl[r][kk + gc + 8];
            }
            #pragma unroll
            for (int nj = 0; nj < 8; nj++) mma16816(acc[nj], ah, bl[nj]);

            al[0] = *(const uint32_t*)&Pl[qb + gr    ][kk + gc];
            al[1] = *(const uint32_t*)&Pl[qb + gr + 8][kk + gc];
            al[2] = *(const uint32_t*)&Pl[qb + gr    ][kk + gc + 8];
            al[3] = *(const uint32_t*)&Pl[qb + gr + 8][kk + gc + 8];
            #pragma unroll
            for (int nj = 0; nj < 8; nj++) mma16816(acc[nj], al, bh[nj]);
        }
    }

    // ---- rowsum combine: pair (t, t^1) shares a row ----
    rsum += __shfl_xor_sync(0xffffffffu, rsum, 1);
    if ((t & 1) == 0) lsum[prow] = rsum;
    __syncthreads();

    const int qb = wid * 16;
    const float inv0 = 1.f / lsum[qb + gr];
    const float inv1 = 1.f / lsum[qb + gr + 8];
    #pragma unroll
    for (int nj = 0; nj < 8; nj++) {
        int dk = nj * 8 + gc;
        size_t o0 = ((size_t)(b * SS + q0 + qb + gr)) * DD + h * 64 + dk;
        size_t o1 = ((size_t)(b * SS + q0 + qb + gr + 8)) * DD + h * 64 + dk;
        *(float2*)&g_x[o0] = make_float2(acc[nj][0] * inv0, acc[nj][1] * inv0);
        *(float2*)&g_x[o1] = make_float2(acc[nj][2] * inv1, acc[nj][3] * inv1);
    }
}

extern "C" void kernel_launch(void* const* d_in, const int* in_sizes, int n_in,
                              void* d_out, int out_size)
{
    // metadata order: query, key, value, bias, mask, W_v, b_v, W_o, b_o
    const float* value = (const float*)d_in[2];
    const float* bias  = (const float*)d_in[3];
    const int*   mask  = (const int*)  d_in[4];
    const float* W_v   = (const float*)d_in[5];
    const float* b_v   = (const float*)d_in[6];
    const float* W_o   = (const float*)d_in[7];
    const float* b_o   = (const float*)d_in[8];

    float* out      = (float*)d_out;                 // [B,S,D]
    float* bias_out = out + (size_t)BB * SS * DD;    // [B,H,S,S]

    cudaFuncSetAttribute(attn2, cudaFuncAttributeMaxDynamicSharedMemorySize, ATTN_SMEM);

    // 1) V projection -> g_vh/g_vl [b][h][dk][s] bf16 hi/lo (HMMA)
    gemm_mma<0><<<dim3(4, 32), 256>>>(value, W_v, b_v, nullptr);

    // 2) masked softmax(bias) @ v  (+ fused bias copy) -> g_x (HMMA)
    attn2<<<dim3(SS / 128, HH, BB), 256, ATTN_SMEM>>>(bias, mask, bias_out);

    // 3) O projection -> out (HMMA)
    gemm_mma<1><<<dim3(4, 32), 256>>>(nullptr, W_o, b_o, out);
}

// round 5
// speedup vs baseline: 2.0300x; 1.4061x over previous
#include <cuda_runtime.h>
#include <cuda_bf16.h>
#include <stdint.h>
#include <math.h>

#define BB 4
#define HH 8
#define SS 1024
#define DD 512
#define DKK 64

// Scratch (allocation-free rule: __device__ globals)
// V projected, pre-split bf16 hi/lo, TRANSPOSED layout [b][h][dk][s]
__device__ __nv_bfloat16 g_vh[BB*HH*DKK*SS];
__device__ __nv_bfloat16 g_vl[BB*HH*DKK*SS];
__device__ float g_x[BB*SS*DD];       // attention output, layout [b][s][h*64+dk]

// bf16 hi/lo split helpers
__device__ __forceinline__ uint32_t pack_bf(__nv_bfloat16 a, __nv_bfloat16 b) {
    return (uint32_t)__bfloat16_as_ushort(a) | ((uint32_t)__bfloat16_as_ushort(b) << 16);
}
__device__ __forceinline__ void split1(float x, __nv_bfloat16& h, __nv_bfloat16& l) {
    h = __float2bfloat16(x);
    l = __float2bfloat16(x - __bfloat162float(h));
}

__device__ __forceinline__ void mma16816(float* d, const uint32_t* a, const uint32_t* b) {
    asm volatile(
        "mma.sync.aligned.m16n8k16.row.col.f32.bf16.bf16.f32 "
        "{%0,%1,%2,%3}, {%4,%5,%6,%7}, {%8,%9}, {%0,%1,%2,%3};"
        : "+f"(d[0]), "+f"(d[1]), "+f"(d[2]), "+f"(d[3])
        : "r"(a[0]), "r"(a[1]), "r"(a[2]), "r"(a[3]), "r"(b[0]), "r"(b[1]));
}

__device__ __forceinline__ uint32_t smem_u32(const void* p) {
    uint32_t a;
    asm("{ .reg .u64 t; cvta.to.shared.u64 t, %1; cvt.u32.u64 %0, t; }" : "=r"(a) : "l"(p));
    return a;
}
__device__ __forceinline__ void cp16(void* s, const void* g) {
    uint32_t sa = smem_u32(s);
    asm volatile("cp.async.cg.shared.global [%0], [%1], 16;" :: "r"(sa), "l"(g));
}
#define CP_COMMIT() asm volatile("cp.async.commit_group;" ::: "memory")

// ================= tensor-core GEMM via mma.sync (HMMA, bf16 hi/lo split) ==========
#define AST 40

template<int MODE>
__global__ void __launch_bounds__(256) gemm_mma(const float* __restrict__ Ain,
                                                const float* __restrict__ W,
                                                const float* __restrict__ bv,
                                                float* __restrict__ Cout)
{
    __shared__ __align__(16) __nv_bfloat16 Ahi[128][AST];
    __shared__ __align__(16) __nv_bfloat16 Alo[128][AST];
    __shared__ __align__(16) __nv_bfloat16 Bhi[128][AST];
    __shared__ __align__(16) __nv_bfloat16 Blo[128][AST];

    const int t = threadIdx.x, wid = t >> 5, lane = t & 31;
    const int wm = wid & 3, wn = wid >> 2;
    const int n0 = blockIdx.x * 128, m0 = blockIdx.y * 128;
    const int gr = lane >> 2, gc = (lane & 3) * 2;
    const float* __restrict__ A = (MODE == 0) ? Ain : g_x;

    float acc[2][8][4];
    #pragma unroll
    for (int i = 0; i < 2; i++)
        #pragma unroll
        for (int j = 0; j < 8; j++)
            #pragma unroll
            for (int q = 0; q < 4; q++) acc[i][j][q] = 0.f;

    for (int k0 = 0; k0 < 512; k0 += 32) {
        #pragma unroll
        for (int it = 0; it < 4; it++) {
            int g = t + it * 256;
            int row = g >> 3, grp = g & 7;
            {
                float4 v4 = *(const float4*)&A[(size_t)(m0 + row) * 512 + k0 + grp * 4];
                __nv_bfloat16 h0,h1,h2,h3,l0,l1,l2,l3;
                split1(v4.x,h0,l0); split1(v4.y,h1,l1); split1(v4.z,h2,l2); split1(v4.w,h3,l3);
                *(uint2*)&Ahi[row][grp*4] = make_uint2(pack_bf(h0,h1), pack_bf(h2,h3));
                *(uint2*)&Alo[row][grp*4] = make_uint2(pack_bf(l0,l1), pack_bf(l2,l3));
            }
            {
                float4 v4 = *(const float4*)&W[(size_t)(n0 + row) * 512 + k0 + grp * 4];
                __nv_bfloat16 h0,h1,h2,h3,l0,l1,l2,l3;
                split1(v4.x,h0,l0); split1(v4.y,h1,l1); split1(v4.z,h2,l2); split1(v4.w,h3,l3);
                *(uint2*)&Bhi[row][grp*4] = make_uint2(pack_bf(h0,h1), pack_bf(h2,h3));
                *(uint2*)&Blo[row][grp*4] = make_uint2(pack_bf(l0,l1), pack_bf(l2,l3));
            }
        }
        __syncthreads();

        #pragma unroll
        for (int kk = 0; kk < 32; kk += 16) {
            uint32_t ah[2][4], al[2][4], bh[8][2], bl[8][2];
            #pragma unroll
            for (int mi = 0; mi < 2; mi++) {
                int r = wm * 32 + mi * 16 + gr;
                ah[mi][0] = *(const uint32_t*)&Ahi[r    ][kk + gc];
                ah[mi][1] = *(const uint32_t*)&Ahi[r + 8][kk + gc];
                ah[mi][2] = *(const uint32_t*)&Ahi[r    ][kk + gc + 8];
                ah[mi][3] = *(const uint32_t*)&Ahi[r + 8][kk + gc + 8];
            }
            #pragma unroll
            for (int nj = 0; nj < 8; nj++) {
                int r = wn * 64 + nj * 8 + gr;
                bh[nj][0] = *(const uint32_t*)&Bhi[r][kk + gc];
                bh[nj][1] = *(const uint32_t*)&Bhi[r][kk + gc + 8];
            }
            #pragma unroll
            for (int mi = 0; mi < 2; mi++)
                #pragma unroll
                for (int nj = 0; nj < 8; nj++) mma16816(acc[mi][nj], ah[mi], bh[nj]);

            #pragma unroll
            for (int nj = 0; nj < 8; nj++) {
                int r = wn * 64 + nj * 8 + gr;
                bl[nj][0] = *(const uint32_t*)&Blo[r][kk + gc];
                bl[nj][1] = *(const uint32_t*)&Blo[r][kk + gc + 8];
            }
            #pragma unroll
            for (int mi = 0; mi < 2; mi++)
                #pragma unroll
                for (int nj = 0; nj < 8; nj++) mma16816(acc[mi][nj], ah[mi], bl[nj]);

            #pragma unroll
            for (int mi = 0; mi < 2; mi++) {
                int r = wm * 32 + mi * 16 + gr;
                al[mi][0] = *(const uint32_t*)&Alo[r    ][kk + gc];
                al[mi][1] = *(const uint32_t*)&Alo[r + 8][kk + gc];
                al[mi][2] = *(const uint32_t*)&Alo[r    ][kk + gc + 8];
                al[mi][3] = *(const uint32_t*)&Alo[r + 8][kk + gc + 8];
            }
            #pragma unroll
            for (int mi = 0; mi < 2; mi++)
                #pragma unroll
                for (int nj = 0; nj < 8; nj++) mma16816(acc[mi][nj], al[mi], bh[nj]);
        }
        __syncthreads();
    }

    #pragma unroll
    for (int mi = 0; mi < 2; mi++) {
        int r0 = m0 + wm * 32 + mi * 16 + gr;
        #pragma unroll
        for (int nj = 0; nj < 8; nj++) {
            int n = n0 + wn * 64 + nj * 8 + gc;
            float v00 = acc[mi][nj][0] + bv[n];
            float v01 = acc[mi][nj][1] + bv[n + 1];
            float v10 = acc[mi][nj][2] + bv[n];
            float v11 = acc[mi][nj][3] + bv[n + 1];
            if (MODE == 0) {
                int h_ = n >> 6, d_ = n & 63;
                int b0_ = r0 >> 10, s0_ = r0 & 1023;
                int b1_ = (r0 + 8) >> 10, s1_ = (r0 + 8) & 1023;
                size_t p00 = (((size_t)(b0_ * HH + h_) * DKK) + d_) * SS + s0_;
                size_t p01 = (((size_t)(b0_ * HH + h_) * DKK) + d_ + 1) * SS + s0_;
                size_t p10 = (((size_t)(b1_ * HH + h_) * DKK) + d_) * SS + s1_;
                size_t p11 = (((size_t)(b1_ * HH + h_) * DKK) + d_ + 1) * SS + s1_;
                __nv_bfloat16 hh, ll;
                split1(v00, hh, ll); g_vh[p00] = hh; g_vl[p00] = ll;
                split1(v01, hh, ll); g_vh[p01] = hh; g_vl[p01] = ll;
                split1(v10, hh, ll); g_vh[p10] = hh; g_vl[p10] = ll;
                split1(v11, hh, ll); g_vh[p11] = hh; g_vl[p11] = ll;
            } else {
                Cout[(size_t)r0 * 512 + n]           = v00;
                Cout[(size_t)r0 * 512 + n + 1]       = v01;
                Cout[(size_t)(r0 + 8) * 512 + n]     = v10;
                Cout[(size_t)(r0 + 8) * 512 + n + 1] = v11;
            }
        }
    }
}

// ============== attention v3: cp.async double-buffered, HMMA PV, no-max softmax ======
// CTA = 64 q rows (grid 16x8x4 = 512), 256 threads, 8 warps (4m x 2n), warp m16n32.
// bias+mask for chunk c+1 staged via cp.async while chunk c computes.
#define PST 72         // P/V smem stride (bf16)
#define SST 68         // stage stride (fp32/int32 elems), 16B-aligned rows
#define STAGE_ELEMS (64 * SST)
#define ATTN_SMEM (4 * STAGE_ELEMS * 4 + 4 * 64 * PST * 2 + 256)

__global__ void __launch_bounds__(256, 2) attn3(const float* __restrict__ bias,
                                                const int*   __restrict__ mask,
                                                float*       __restrict__ bias_out)
{
    extern __shared__ __align__(16) char smem[];
    typedef __nv_bfloat16 bf;
    float* stB  = (float*)smem;                               // 2 stages bias
    int*   stM  = (int*)(smem + 2 * STAGE_ELEMS * 4);         // 2 stages mask
    bf*    Ph   = (bf*)(smem + 4 * STAGE_ELEMS * 4);
    bf*    Pl   = Ph + 64 * PST;
    bf*    Vh   = Pl + 64 * PST;
    bf*    Vl   = Vh + 64 * PST;
    float* lsum = (float*)(Vl + 64 * PST);

    const int t = threadIdx.x, wid = t >> 5, lane = t & 31;
    const int gr = lane >> 2, gc = (lane & 3) * 2;
    const int wm = wid & 3, wn = wid >> 2;
    const int q0 = blockIdx.x * 64;
    const int h  = blockIdx.y;
    const int b  = blockIdx.z;

    const float* __restrict__ bias_base = bias     + (((size_t)(b * HH + h)) * SS + q0) * SS;
    float*       __restrict__ bout_base = bias_out + (((size_t)(b * HH + h)) * SS + q0) * SS;
    const int*   __restrict__ mask_base = mask     + ((size_t)(b * SS + q0)) * SS;
    const bf*    __restrict__ vh_base   = g_vh + ((size_t)(b * HH + h) * DKK) * SS;
    const bf*    __restrict__ vl_base   = g_vl + ((size_t)(b * HH + h) * DKK) * SS;

    const int prow = t >> 2;           // P-gen: row 0..63
    const int pc0  = (t & 3) * 16;     // 16 cols per thread
    const int vrow = t >> 2;           // V load: dk row
    const int vc0  = (t & 3) * 16;

    float rsum = 0.f;
    float acc[4][4];
    #pragma unroll
    for (int j = 0; j < 4; j++)
        #pragma unroll
        for (int q = 0; q < 4; q++) acc[j][q] = 0.f;

    // prefetch chunk 0
    {
        #pragma unroll
        for (int i = 0; i < 4; i++) {
            int o = t + i * 256; int row = o >> 4, seg = o & 15;
            cp16(&stB[row * SST + seg * 4], &bias_base[(size_t)row * SS + seg * 4]);
            cp16(&stM[row * SST + seg * 4], &mask_base[(size_t)row * SS + seg * 4]);
        }
        CP_COMMIT();
    }

    for (int c = 0; c < 16; c++) {
        const int k0 = c * 64;
        // issue stage for chunk c+1
        if (c < 15) {
            float* dB = stB + ((c + 1) & 1) * STAGE_ELEMS;
            int*   dM = stM + ((c + 1) & 1) * STAGE_ELEMS;
            #pragma unroll
            for (int i = 0; i < 4; i++) {
                int o = t + i * 256; int row = o >> 4, seg = o & 15;
                cp16(&dB[row * SST + seg * 4], &bias_base[(size_t)row * SS + k0 + 64 + seg * 4]);
                cp16(&dM[row * SST + seg * 4], &mask_base[(size_t)row * SS + k0 + 64 + seg * 4]);
            }
            CP_COMMIT();
            asm volatile("cp.async.wait_group 1;" ::: "memory");
        } else {
            asm volatile("cp.async.wait_group 0;" ::: "memory");
        }
        __syncthreads();   // stage(c) visible to all; prev MMA done before P overwrite

        // ---- P gen from staged smem (+ bias copy-out) ----
        const float* sB = stB + (c & 1) * STAGE_ELEMS + prow * SST + pc0;
        const int*   sM = stM + (c & 1) * STAGE_ELEMS + prow * SST + pc0;
        float*       bo = bout_base + (size_t)prow * SS + k0 + pc0;
        #pragma unroll
        for (int g = 0; g < 4; g++) {
            float4 b4 = *(const float4*)(sB + g * 4);
            int4   m4 = *(const int4*)(sM + g * 4);
            *(float4*)(bo + g * 4) = b4;
            float p0 = m4.x ? __expf(b4.x) : 0.f;
            float p1 = m4.y ? __expf(b4.y) : 0.f;
            float p2 = m4.z ? __expf(b4.z) : 0.f;
            float p3 = m4.w ? __expf(b4.w) : 0.f;
            rsum += (p0 + p1) + (p2 + p3);
            __nv_bfloat16 h0,h1,h2,h3,l0,l1,l2,l3;
            split1(p0,h0,l0); split1(p1,h1,l1); split1(p2,h2,l2); split1(p3,h3,l3);
            *(uint2*)&Ph[prow * PST + pc0 + g * 4] = make_uint2(pack_bf(h0,h1), pack_bf(h2,h3));
            *(uint2*)&Pl[prow * PST + pc0 + g * 4] = make_uint2(pack_bf(l0,l1), pack_bf(l2,l3));
        }

        // ---- V tile 64(dk) x 64(k): L2-resident, reused 8x across q-blocks ----
        {
            const bf* vh_p = vh_base + (size_t)vrow * SS + k0 + vc0;
            const bf* vl_p = vl_base + (size_t)vrow * SS + k0 + vc0;
            *(uint4*)&Vh[vrow * PST + vc0]     = *(const uint4*)(vh_p);
            *(uint4*)&Vh[vrow * PST + vc0 + 8] = *(const uint4*)(vh_p + 8);
            *(uint4*)&Vl[vrow * PST + vc0]     = *(const uint4*)(vl_p);
            *(uint4*)&Vl[vrow * PST + vc0 + 8] = *(const uint4*)(vl_p + 8);
        }
        __syncthreads();

        // ---- MMA: warp tile m16 x n32, 4 k16 steps, 3 passes ----
        const int qb = wm * 16, vb = wn * 32;
        #pragma unroll
        for (int kk = 0; kk < 64; kk += 16) {
            uint32_t ah[4], al[4], bh[4][2], bl[4][2];
            ah[0] = *(const uint32_t*)&Ph[(qb + gr    ) * PST + kk + gc];
            ah[1] = *(const uint32_t*)&Ph[(qb + gr + 8) * PST + kk + gc];
            ah[2] = *(const uint32_t*)&Ph[(qb + gr    ) * PST + kk + gc + 8];
            ah[3] = *(const uint32_t*)&Ph[(qb + gr + 8) * PST + kk + gc + 8];
            #pragma unroll
            for (int nj = 0; nj < 4; nj++) {
                int r = vb + nj * 8 + gr;
                bh[nj][0] = *(const uint32_t*)&Vh[r * PST + kk + gc];
                bh[nj][1] = *(const uint32_t*)&Vh[r * PST + kk + gc + 8];
            }
            #pragma unroll
            for (int nj = 0; nj < 4; nj++) mma16816(acc[nj], ah, bh[nj]);

            #pragma unroll
            for (int nj = 0; nj < 4; nj++) {
                int r = vb + nj * 8 + gr;
                bl[nj][0] = *(const uint32_t*)&Vl[r * PST + kk + gc];
                bl[nj][1] = *(const uint32_t*)&Vl[r * PST + kk + gc + 8];
            }
            #pragma unroll
            for (int nj = 0; nj < 4; nj++) mma16816(acc[nj], ah, bl[nj]);

            al[0] = *(const uint32_t*)&Pl[(qb + gr    ) * PST + kk + gc];
            al[1] = *(const uint32_t*)&Pl[(qb + gr + 8) * PST + kk + gc];
            al[2] = *(const uint32_t*)&Pl[(qb + gr    ) * PST + kk + gc + 8];
            al[3] = *(const uint32_t*)&Pl[(qb + gr + 8) * PST + kk + gc + 8];
            #pragma unroll
            for (int nj = 0; nj < 4; nj++) mma16816(acc[nj], al, bh[nj]);
        }
    }

    // ---- rowsum combine: 4 threads (t&3) share row prow ----
    rsum += __shfl_xor_sync(0xffffffffu, rsum, 1);
    rsum += __shfl_xor_sync(0xffffffffu, rsum, 2);
    if ((t & 3) == 0) lsum[prow] = rsum;
    __syncthreads();

    const int qb = wm * 16, vb = wn * 32;
    const float inv0 = 1.f / lsum[qb + gr];
    const float inv1 = 1.f / lsum[qb + gr + 8];
    #pragma unroll
    for (int nj = 0; nj < 4; nj++) {
        int dk = vb + nj * 8 + gc;
        size_t o0 = ((size_t)(b * SS + q0 + qb + gr)) * DD + h * 64 + dk;
        size_t o1 = ((size_t)(b * SS + q0 + qb + gr + 8)) * DD + h * 64 + dk;
        *(float2*)&g_x[o0] = make_float2(acc[nj][0] * inv0, acc[nj][1] * inv0);
        *(float2*)&g_x[o1] = make_float2(acc[nj][2] * inv1, acc[nj][3] * inv1);
    }
}

extern "C" void kernel_launch(void* const* d_in, const int* in_sizes, int n_in,
                              void* d_out, int out_size)
{
    // metadata order: query, key, value, bias, mask, W_v, b_v, W_o, b_o
    const float* value = (const float*)d_in[2];
    const float* bias  = (const float*)d_in[3];
    const int*   mask  = (const int*)  d_in[4];
    const float* W_v   = (const float*)d_in[5];
    const float* b_v   = (const float*)d_in[6];
    const float* W_o   = (const float*)d_in[7];
    const float* b_o   = (const float*)d_in[8];

    float* out      = (float*)d_out;                 // [B,S,D]
    float* bias_out = out + (size_t)BB * SS * DD;    // [B,H,S,S]

    cudaFuncSetAttribute(attn3, cudaFuncAttributeMaxDynamicSharedMemorySize, ATTN_SMEM);

    // 1) V projection -> g_vh/g_vl [b][h][dk][s] bf16 hi/lo (HMMA)
    gemm_mma<0><<<dim3(4, 32), 256>>>(value, W_v, b_v, nullptr);

    // 2) masked softmax(bias) @ v  (+ fused bias copy) -> g_x (HMMA, cp.async pipelined)
    attn3<<<dim3(SS / 64, HH, BB), 256, ATTN_SMEM>>>(bias, mask, bias_out);

    // 3) O projection -> out (HMMA)
    gemm_mma<1><<<dim3(4, 32), 256>>>(nullptr, W_o, b_o, out);
}

// round 6
// speedup vs baseline: 2.1156x; 1.0422x over previous
#include <cuda_runtime.h>
#include <cuda_bf16.h>
#include <stdint.h>
#include <math.h>

#define BB 4
#define HH 8
#define SS 1024
#define DD 512
#define DKK 64

// Scratch (allocation-free rule: __device__ globals)
// V projected, pre-split bf16 hi/lo, TRANSPOSED layout [b][h][dk][s]
__device__ __nv_bfloat16 g_vh[BB*HH*DKK*SS];
__device__ __nv_bfloat16 g_vl[BB*HH*DKK*SS];
__device__ float g_x[BB*SS*DD];       // attention output, layout [b][s][h*64+dk]

// bf16 hi/lo split helpers
__device__ __forceinline__ uint32_t pack_bf(__nv_bfloat16 a, __nv_bfloat16 b) {
    return (uint32_t)__bfloat16_as_ushort(a) | ((uint32_t)__bfloat16_as_ushort(b) << 16);
}
__device__ __forceinline__ void split1(float x, __nv_bfloat16& h, __nv_bfloat16& l) {
    h = __float2bfloat16(x);
    l = __float2bfloat16(x - __bfloat162float(h));
}

__device__ __forceinline__ void mma16816(float* d, const uint32_t* a, const uint32_t* b) {
    asm volatile(
        "mma.sync.aligned.m16n8k16.row.col.f32.bf16.bf16.f32 "
        "{%0,%1,%2,%3}, {%4,%5,%6,%7}, {%8,%9}, {%0,%1,%2,%3};"
        : "+f"(d[0]), "+f"(d[1]), "+f"(d[2]), "+f"(d[3])
        : "r"(a[0]), "r"(a[1]), "r"(a[2]), "r"(a[3]), "r"(b[0]), "r"(b[1]));
}

__device__ __forceinline__ uint32_t smem_u32(const void* p) {
    uint32_t a;
    asm("{ .reg .u64 t; cvta.to.shared.u64 t, %1; cvt.u32.u64 %0, t; }" : "=r"(a) : "l"(p));
    return a;
}
__device__ __forceinline__ void cp16(void* s, const void* g) {
    uint32_t sa = smem_u32(s);
    asm volatile("cp.async.cg.shared.global [%0], [%1], 16;" :: "r"(sa), "l"(g));
}
#define CP_COMMIT() asm volatile("cp.async.commit_group;" ::: "memory")

// ================= tensor-core GEMM, cp.async double-buffered =====================
// C = A @ W^T + bv. A:[4096,512], W:[512,512] row-major. CTA 128x128, K chunk 32.
// fp32 tiles staged via cp.async (2 stages); convert to bf16 hi/lo in smem; 3-pass HMMA.
#define AST 40              // split-buffer stride (bf16)
#define GST 36              // fp32 stage stride (floats, 16B-aligned, conflict-free)
#define GSTAGE (128 * GST)  // floats per stage tile
#define GEMM_SMEM (4 * GSTAGE * 4 + 4 * 128 * AST * 2 + 16)

template<int MODE>
__global__ void __launch_bounds__(256) gemm_mma(const float* __restrict__ Ain,
                                                const float* __restrict__ W,
                                                const float* __restrict__ bv,
                                                float* __restrict__ Cout)
{
    extern __shared__ __align__(16) char smem[];
    typedef __nv_bfloat16 bf;
    float* stA = (float*)smem;                       // 2 stages A (fp32 128x32)
    float* stW = stA + 2 * GSTAGE;                   // 2 stages W
    bf*    Ahi = (bf*)(stW + 2 * GSTAGE);
    bf*    Alo = Ahi + 128 * AST;
    bf*    Bhi = Alo + 128 * AST;
    bf*    Blo = Bhi + 128 * AST;

    const int t = threadIdx.x, wid = t >> 5, lane = t & 31;
    const int wm = wid & 3, wn = wid >> 2;
    const int n0 = blockIdx.x * 128, m0 = blockIdx.y * 128;
    const int gr = lane >> 2, gc = (lane & 3) * 2;
    const float* __restrict__ A = (MODE == 0) ? Ain : g_x;

    float acc[2][8][4];
    #pragma unroll
    for (int i = 0; i < 2; i++)
        #pragma unroll
        for (int j = 0; j < 8; j++)
            #pragma unroll
            for (int q = 0; q < 4; q++) acc[i][j][q] = 0.f;

    // prefetch chunk 0: 128 rows x 32 cols (8 cp16 segments per row)
    {
        #pragma unroll
        for (int i = 0; i < 4; i++) {
            int g = t + i * 256;               // 1024 segments
            int row = g >> 3, seg = g & 7;
            cp16(&stA[row * GST + seg * 4], &A[(size_t)(m0 + row) * 512 + seg * 4]);
            cp16(&stW[row * GST + seg * 4], &W[(size_t)(n0 + row) * 512 + seg * 4]);
        }
        CP_COMMIT();
    }

    for (int c = 0; c < 16; c++) {
        // issue stage for chunk c+1
        if (c < 15) {
            float* dA = stA + ((c + 1) & 1) * GSTAGE;
            float* dW = stW + ((c + 1) & 1) * GSTAGE;
            const int k1 = (c + 1) * 32;
            #pragma unroll
            for (int i = 0; i < 4; i++) {
                int g = t + i * 256;
                int row = g >> 3, seg = g & 7;
                cp16(&dA[row * GST + seg * 4], &A[(size_t)(m0 + row) * 512 + k1 + seg * 4]);
                cp16(&dW[row * GST + seg * 4], &W[(size_t)(n0 + row) * 512 + k1 + seg * 4]);
            }
            CP_COMMIT();
            asm volatile("cp.async.wait_group 1;" ::: "memory");
        } else {
            asm volatile("cp.async.wait_group 0;" ::: "memory");
        }
        __syncthreads();   // stage(c) ready; also orders prev MMA before convert overwrite

        // ---- convert stage(c) fp32 -> bf16 hi/lo split buffers ----
        const float* sA = stA + (c & 1) * GSTAGE;
        const float* sW = stW + (c & 1) * GSTAGE;
        #pragma unroll
        for (int i = 0; i < 4; i++) {
            int g = t + i * 256;
            int row = g >> 3, grp = g & 7;
            {
                float4 v4 = *(const float4*)&sA[row * GST + grp * 4];
                __nv_bfloat16 h0,h1,h2,h3,l0,l1,l2,l3;
                split1(v4.x,h0,l0); split1(v4.y,h1,l1); split1(v4.z,h2,l2); split1(v4.w,h3,l3);
                *(uint2*)&Ahi[row * AST + grp * 4] = make_uint2(pack_bf(h0,h1), pack_bf(h2,h3));
                *(uint2*)&Alo[row * AST + grp * 4] = make_uint2(pack_bf(l0,l1), pack_bf(l2,l3));
            }
            {
                float4 v4 = *(const float4*)&sW[row * GST + grp * 4];
                __nv_bfloat16 h0,h1,h2,h3,l0,l1,l2,l3;
                split1(v4.x,h0,l0); split1(v4.y,h1,l1); split1(v4.z,h2,l2); split1(v4.w,h3,l3);
                *(uint2*)&Bhi[row * AST + grp * 4] = make_uint2(pack_bf(h0,h1), pack_bf(h2,h3));
                *(uint2*)&Blo[row * AST + grp * 4] = make_uint2(pack_bf(l0,l1), pack_bf(l2,l3));
            }
        }
        __syncthreads();

        // ---- 3-pass MMA over 2 k16 steps ----
        #pragma unroll
        for (int kk = 0; kk < 32; kk += 16) {
            uint32_t ah[2][4], al[2][4], bh[8][2], bl[8][2];
            #pragma unroll
            for (int mi = 0; mi < 2; mi++) {
                int r = wm * 32 + mi * 16 + gr;
                ah[mi][0] = *(const uint32_t*)&Ahi[(r    ) * AST + kk + gc];
                ah[mi][1] = *(const uint32_t*)&Ahi[(r + 8) * AST + kk + gc];
                ah[mi][2] = *(const uint32_t*)&Ahi[(r    ) * AST + kk + gc + 8];
                ah[mi][3] = *(const uint32_t*)&Ahi[(r + 8) * AST + kk + gc + 8];
            }
            #pragma unroll
            for (int nj = 0; nj < 8; nj++) {
                int r = wn * 64 + nj * 8 + gr;
                bh[nj][0] = *(const uint32_t*)&Bhi[r * AST + kk + gc];
                bh[nj][1] = *(const uint32_t*)&Bhi[r * AST + kk + gc + 8];
            }
            #pragma unroll
            for (int mi = 0; mi < 2; mi++)
                #pragma unroll
                for (int nj = 0; nj < 8; nj++) mma16816(acc[mi][nj], ah[mi], bh[nj]);

            #pragma unroll
            for (int nj = 0; nj < 8; nj++) {
                int r = wn * 64 + nj * 8 + gr;
                bl[nj][0] = *(const uint32_t*)&Blo[r * AST + kk + gc];
                bl[nj][1] = *(const uint32_t*)&Blo[r * AST + kk + gc + 8];
            }
            #pragma unroll
            for (int mi = 0; mi < 2; mi++)
                #pragma unroll
                for (int nj = 0; nj < 8; nj++) mma16816(acc[mi][nj], ah[mi], bl[nj]);

            #pragma unroll
            for (int mi = 0; mi < 2; mi++) {
                int r = wm * 32 + mi * 16 + gr;
                al[mi][0] = *(const uint32_t*)&Alo[(r    ) * AST + kk + gc];
                al[mi][1] = *(const uint32_t*)&Alo[(r + 8) * AST + kk + gc];
                al[mi][2] = *(const uint32_t*)&Alo[(r    ) * AST + kk + gc + 8];
                al[mi][3] = *(const uint32_t*)&Alo[(r + 8) * AST + kk + gc + 8];
            }
            #pragma unroll
            for (int mi = 0; mi < 2; mi++)
                #pragma unroll
                for (int nj = 0; nj < 8; nj++) mma16816(acc[mi][nj], al[mi], bh[nj]);
        }
    }

    // ---- epilogue ----
    #pragma unroll
    for (int mi = 0; mi < 2; mi++) {
        int r0 = m0 + wm * 32 + mi * 16 + gr;
        #pragma unroll
        for (int nj = 0; nj < 8; nj++) {
            int n = n0 + wn * 64 + nj * 8 + gc;
            float v00 = acc[mi][nj][0] + bv[n];
            float v01 = acc[mi][nj][1] + bv[n + 1];
            float v10 = acc[mi][nj][2] + bv[n];
            float v11 = acc[mi][nj][3] + bv[n + 1];
            if (MODE == 0) {
                int h_ = n >> 6, d_ = n & 63;
                int b0_ = r0 >> 10, s0_ = r0 & 1023;
                int b1_ = (r0 + 8) >> 10, s1_ = (r0 + 8) & 1023;
                size_t p00 = (((size_t)(b0_ * HH + h_) * DKK) + d_) * SS + s0_;
                size_t p01 = (((size_t)(b0_ * HH + h_) * DKK) + d_ + 1) * SS + s0_;
                size_t p10 = (((size_t)(b1_ * HH + h_) * DKK) + d_) * SS + s1_;
                size_t p11 = (((size_t)(b1_ * HH + h_) * DKK) + d_ + 1) * SS + s1_;
                __nv_bfloat16 hh, ll;
                split1(v00, hh, ll); g_vh[p00] = hh; g_vl[p00] = ll;
                split1(v01, hh, ll); g_vh[p01] = hh; g_vl[p01] = ll;
                split1(v10, hh, ll); g_vh[p10] = hh; g_vl[p10] = ll;
                split1(v11, hh, ll); g_vh[p11] = hh; g_vl[p11] = ll;
            } else {
                Cout[(size_t)r0 * 512 + n]           = v00;
                Cout[(size_t)r0 * 512 + n + 1]       = v01;
                Cout[(size_t)(r0 + 8) * 512 + n]     = v10;
                Cout[(size_t)(r0 + 8) * 512 + n + 1] = v11;
            }
        }
    }
}

// ============== attention v3: cp.async double-buffered, HMMA PV, no-max softmax ======
#define PST 72
#define SST 68
#define STAGE_ELEMS (64 * SST)
#define ATTN_SMEM (4 * STAGE_ELEMS * 4 + 4 * 64 * PST * 2 + 256)

__global__ void __launch_bounds__(256, 2) attn3(const float* __restrict__ bias,
                                                const int*   __restrict__ mask,
                                                float*       __restrict__ bias_out)
{
    extern __shared__ __align__(16) char smem[];
    typedef __nv_bfloat16 bf;
    float* stB  = (float*)smem;
    int*   stM  = (int*)(smem + 2 * STAGE_ELEMS * 4);
    bf*    Ph   = (bf*)(smem + 4 * STAGE_ELEMS * 4);
    bf*    Pl   = Ph + 64 * PST;
    bf*    Vh   = Pl + 64 * PST;
    bf*    Vl   = Vh + 64 * PST;
    float* lsum = (float*)(Vl + 64 * PST);

    const int t = threadIdx.x, wid = t >> 5, lane = t & 31;
    const int gr = lane >> 2, gc = (lane & 3) * 2;
    const int wm = wid & 3, wn = wid >> 2;
    const int q0 = blockIdx.x * 64;
    const int h  = blockIdx.y;
    const int b  = blockIdx.z;

    const float* __restrict__ bias_base = bias     + (((size_t)(b * HH + h)) * SS + q0) * SS;
    float*       __restrict__ bout_base = bias_out + (((size_t)(b * HH + h)) * SS + q0) * SS;
    const int*   __restrict__ mask_base = mask     + ((size_t)(b * SS + q0)) * SS;
    const bf*    __restrict__ vh_base   = g_vh + ((size_t)(b * HH + h) * DKK) * SS;
    const bf*    __restrict__ vl_base   = g_vl + ((size_t)(b * HH + h) * DKK) * SS;

    const int prow = t >> 2;
    const int pc0  = (t & 3) * 16;
    const int vrow = t >> 2;
    const int vc0  = (t & 3) * 16;

    float rsum = 0.f;
    float acc[4][4];
    #pragma unroll
    for (int j = 0; j < 4; j++)
        #pragma unroll
        for (int q = 0; q < 4; q++) acc[j][q] = 0.f;

    {
        #pragma unroll
        for (int i = 0; i < 4; i++) {
            int o = t + i * 256; int row = o >> 4, seg = o & 15;
            cp16(&stB[row * SST + seg * 4], &bias_base[(size_t)row * SS + seg * 4]);
            cp16(&stM[row * SST + seg * 4], &mask_base[(size_t)row * SS + seg * 4]);
        }
        CP_COMMIT();
    }

    for (int c = 0; c < 16; c++) {
        const int k0 = c * 64;
        if (c < 15) {
            float* dB = stB + ((c + 1) & 1) * STAGE_ELEMS;
            int*   dM = stM + ((c + 1) & 1) * STAGE_ELEMS;
            #pragma unroll
            for (int i = 0; i < 4; i++) {
                int o = t + i * 256; int row = o >> 4, seg = o & 15;
                cp16(&dB[row * SST + seg * 4], &bias_base[(size_t)row * SS + k0 + 64 + seg * 4]);
                cp16(&dM[row * SST + seg * 4], &mask_base[(size_t)row * SS + k0 + 64 + seg * 4]);
            }
            CP_COMMIT();
            asm volatile("cp.async.wait_group 1;" ::: "memory");
        } else {
            asm volatile("cp.async.wait_group 0;" ::: "memory");
        }
        __syncthreads();

        const float* sB = stB + (c & 1) * STAGE_ELEMS + prow * SST + pc0;
        const int*   sM = stM + (c & 1) * STAGE_ELEMS + prow * SST + pc0;
        float*       bo = bout_base + (size_t)prow * SS + k0 + pc0;
        #pragma unroll
        for (int g = 0; g < 4; g++) {
            float4 b4 = *(const float4*)(sB + g * 4);
            int4   m4 = *(const int4*)(sM + g * 4);
            *(float4*)(bo + g * 4) = b4;
            float p0 = m4.x ? __expf(b4.x) : 0.f;
            float p1 = m4.y ? __expf(b4.y) : 0.f;
            float p2 = m4.z ? __expf(b4.z) : 0.f;
            float p3 = m4.w ? __expf(b4.w) : 0.f;
            rsum += (p0 + p1) + (p2 + p3);
            __nv_bfloat16 h0,h1,h2,h3,l0,l1,l2,l3;
            split1(p0,h0,l0); split1(p1,h1,l1); split1(p2,h2,l2); split1(p3,h3,l3);
            *(uint2*)&Ph[prow * PST + pc0 + g * 4] = make_uint2(pack_bf(h0,h1), pack_bf(h2,h3));
            *(uint2*)&Pl[prow * PST + pc0 + g * 4] = make_uint2(pack_bf(l0,l1), pack_bf(l2,l3));
        }

        {
            const bf* vh_p = vh_base + (size_t)vrow * SS + k0 + vc0;
            const bf* vl_p = vl_base + (size_t)vrow * SS + k0 + vc0;
            *(uint4*)&Vh[vrow * PST + vc0]     = *(const uint4*)(vh_p);
            *(uint4*)&Vh[vrow * PST + vc0 + 8] = *(const uint4*)(vh_p + 8);
            *(uint4*)&Vl[vrow * PST + vc0]     = *(const uint4*)(vl_p);
            *(uint4*)&Vl[vrow * PST + vc0 + 8] = *(const uint4*)(vl_p + 8);
        }
        __syncthreads();

        const int qb = wm * 16, vb = wn * 32;
        #pragma unroll
        for (int kk = 0; kk < 64; kk += 16) {
            uint32_t ah[4], al[4], bh[4][2], bl[4][2];
            ah[0] = *(const uint32_t*)&Ph[(qb + gr    ) * PST + kk + gc];
            ah[1] = *(const uint32_t*)&Ph[(qb + gr + 8) * PST + kk + gc];
            ah[2] = *(const uint32_t*)&Ph[(qb + gr    ) * PST + kk + gc + 8];
            ah[3] = *(const uint32_t*)&Ph[(qb + gr + 8) * PST + kk + gc + 8];
            #pragma unroll
            for (int nj = 0; nj < 4; nj++) {
                int r = vb + nj * 8 + gr;
                bh[nj][0] = *(const uint32_t*)&Vh[r * PST + kk + gc];
                bh[nj][1] = *(const uint32_t*)&Vh[r * PST + kk + gc + 8];
            }
            #pragma unroll
            for (int nj = 0; nj < 4; nj++) mma16816(acc[nj], ah, bh[nj]);

            #pragma unroll
            for (int nj = 0; nj < 4; nj++) {
                int r = vb + nj * 8 + gr;
                bl[nj][0] = *(const uint32_t*)&Vl[r * PST + kk + gc];
                bl[nj][1] = *(const uint32_t*)&Vl[r * PST + kk + gc + 8];
            }
            #pragma unroll
            for (int nj = 0; nj < 4; nj++) mma16816(acc[nj], ah, bl[nj]);

            al[0] = *(const uint32_t*)&Pl[(qb + gr    ) * PST + kk + gc];
            al[1] = *(const uint32_t*)&Pl[(qb + gr + 8) * PST + kk + gc];
            al[2] = *(const uint32_t*)&Pl[(qb + gr    ) * PST + kk + gc + 8];
            al[3] = *(const uint32_t*)&Pl[(qb + gr + 8) * PST + kk + gc + 8];
            #pragma unroll
            for (int nj = 0; nj < 4; nj++) mma16816(acc[nj], al, bh[nj]);
        }
    }

    rsum += __shfl_xor_sync(0xffffffffu, rsum, 1);
    rsum += __shfl_xor_sync(0xffffffffu, rsum, 2);
    if ((t & 3) == 0) lsum[prow] = rsum;
    __syncthreads();

    const int qb = wm * 16, vb = wn * 32;
    const float inv0 = 1.f / lsum[qb + gr];
    const float inv1 = 1.f / lsum[qb + gr + 8];
    #pragma unroll
    for (int nj = 0; nj < 4; nj++) {
        int dk = vb + nj * 8 + gc;
        size_t o0 = ((size_t)(b * SS + q0 + qb + gr)) * DD + h * 64 + dk;
        size_t o1 = ((size_t)(b * SS + q0 + qb + gr + 8)) * DD + h * 64 + dk;
        *(float2*)&g_x[o0] = make_float2(acc[nj][0] * inv0, acc[nj][1] * inv0);
        *(float2*)&g_x[o1] = make_float2(acc[nj][2] * inv1, acc[nj][3] * inv1);
    }
}

extern "C" void kernel_launch(void* const* d_in, const int* in_sizes, int n_in,
                              void* d_out, int out_size)
{
    // metadata order: query, key, value, bias, mask, W_v, b_v, W_o, b_o
    const float* value = (const float*)d_in[2];
    const float* bias  = (const float*)d_in[3];
    const int*   mask  = (const int*)  d_in[4];
    const float* W_v   = (const float*)d_in[5];
    const float* b_v   = (const float*)d_in[6];
    const float* W_o   = (const float*)d_in[7];
    const float* b_o   = (const float*)d_in[8];

    float* out      = (float*)d_out;                 // [B,S,D]
    float* bias_out = out + (size_t)BB * SS * DD;    // [B,H,S,S]

    cudaFuncSetAttribute(gemm_mma<0>, cudaFuncAttributeMaxDynamicSharedMemorySize, GEMM_SMEM);
    cudaFuncSetAttribute(gemm_mma<1>, cudaFuncAttributeMaxDynamicSharedMemorySize, GEMM_SMEM);
    cudaFuncSetAttribute(attn3, cudaFuncAttributeMaxDynamicSharedMemorySize, ATTN_SMEM);

    // 1) V projection -> g_vh/g_vl [b][h][dk][s] bf16 hi/lo (HMMA, pipelined)
    gemm_mma<0><<<dim3(4, 32), 256, GEMM_SMEM>>>(value, W_v, b_v, nullptr);

    // 2) masked softmax(bias) @ v  (+ fused bias copy) -> g_x (HMMA, pipelined)
    attn3<<<dim3(SS / 64, HH, BB), 256, ATTN_SMEM>>>(bias, mask, bias_out);

    // 3) O projection -> out (HMMA, pipelined)
    gemm_mma<1><<<dim3(4, 32), 256, GEMM_SMEM>>>(nullptr, W_o, b_o, out);
}

// round 7
// speedup vs baseline: 2.3073x; 1.0906x over previous
#include <cuda_runtime.h>
#include <cuda_bf16.h>
#include <stdint.h>
#include <math.h>

#define BB 4
#define HH 8
#define SS 1024
#define DD 512
#define DKK 64

typedef __nv_bfloat16 bf;

// Scratch (allocation-free rule: __device__ globals)
__device__ bf g_vh[BB*HH*DKK*SS];   // V projected, split hi, transposed [b][h][dk][s]
__device__ bf g_vl[BB*HH*DKK*SS];   // V projected, split lo
__device__ bf g_xh[BB*SS*DD];       // attn out, split hi, [b][s][h*64+dk]
__device__ bf g_xl[BB*SS*DD];       // attn out, split lo
__device__ bf g_ah[BB*SS*DD];       // value pre-split hi
__device__ bf g_al[BB*SS*DD];       // value pre-split lo
__device__ bf g_wvh[DD*DD];         // W_v pre-split
__device__ bf g_wvl[DD*DD];
__device__ bf g_woh[DD*DD];         // W_o pre-split
__device__ bf g_wol[DD*DD];

__device__ __forceinline__ uint32_t pack_bf(bf a, bf b) {
    return (uint32_t)__bfloat16_as_ushort(a) | ((uint32_t)__bfloat16_as_ushort(b) << 16);
}
__device__ __forceinline__ void split1(float x, bf& h, bf& l) {
    h = __float2bfloat16(x);
    l = __float2bfloat16(x - __bfloat162float(h));
}

__device__ __forceinline__ void mma16816(float* d, const uint32_t* a, const uint32_t* b) {
    asm volatile(
        "mma.sync.aligned.m16n8k16.row.col.f32.bf16.bf16.f32 "
        "{%0,%1,%2,%3}, {%4,%5,%6,%7}, {%8,%9}, {%0,%1,%2,%3};"
        : "+f"(d[0]), "+f"(d[1]), "+f"(d[2]), "+f"(d[3])
        : "r"(a[0]), "r"(a[1]), "r"(a[2]), "r"(a[3]), "r"(b[0]), "r"(b[1]));
}

__device__ __forceinline__ uint32_t smem_u32(const void* p) {
    uint32_t a;
    asm("{ .reg .u64 t; cvta.to.shared.u64 t, %1; cvt.u32.u64 %0, t; }" : "=r"(a) : "l"(p));
    return a;
}
__device__ __forceinline__ void cp16(void* s, const void* g) {
    uint32_t sa = smem_u32(s);
    asm volatile("cp.async.cg.shared.global [%0], [%1], 16;" :: "r"(sa), "l"(g));
}
#define CP_COMMIT() asm volatile("cp.async.commit_group;" ::: "memory")

// ======================= prep: fp32 -> bf16 hi/lo split =======================
#define N_A4 (BB*SS*DD/4)      // 524288 float4 of value
#define N_W4 (DD*DD/4)         // 65536 float4 per W
__global__ void __launch_bounds__(256) split_prep(const float* __restrict__ value,
                                                  const float* __restrict__ Wv,
                                                  const float* __restrict__ Wo)
{
    int i = blockIdx.x * 256 + threadIdx.x;
    const float* src; bf *dh, *dl; int base;
    if (i < N_A4)            { src = value; dh = g_ah;  dl = g_al;  base = i; }
    else if (i < N_A4+N_W4)  { src = Wv;    dh = g_wvh; dl = g_wvl; base = i - N_A4; }
    else                     { src = Wo;    dh = g_woh; dl = g_wol; base = i - N_A4 - N_W4; }
    float4 v = ((const float4*)src)[base];
    bf h0,h1,h2,h3,l0,l1,l2,l3;
    split1(v.x,h0,l0); split1(v.y,h1,l1); split1(v.z,h2,l2); split1(v.w,h3,l3);
    *(uint2*)&dh[(size_t)base*4] = make_uint2(pack_bf(h0,h1), pack_bf(h2,h3));
    *(uint2*)&dl[(size_t)base*4] = make_uint2(pack_bf(l0,l1), pack_bf(l2,l3));
}

// ============== tensor-core GEMM on pre-split bf16, 4-slot cp.async ring =========
// C = A @ W^T + bv, all operands pre-split bf16 hi/lo. CTA 128x128, K chunk 32,
// 4-slot ring (depth-2 prefetch), ONE barrier per chunk, no in-loop conversion.
// MODE 0: scatter into g_vh/g_vl [b][h][dk][s]. MODE 1: Cout fp32 rows.
#define AST 40                       // bf16 row stride (80B: 16B-aligned, conflict-free)
#define GBUF (128 * AST)             // bf16 elems per buffer
#define GSLOT (4 * GBUF)             // Ahi,Alo,Whi,Wlo
#define GEMM_SMEM (4 * GSLOT * 2)    // 4 slots * 40960B = 163840

template<int MODE>
__global__ void __launch_bounds__(256) gemm_bf(const bf* __restrict__ Ah,
                                               const bf* __restrict__ Al,
                                               const bf* __restrict__ Wh,
                                               const bf* __restrict__ Wl,
                                               const float* __restrict__ bv,
                                               float* __restrict__ Cout)
{
    extern __shared__ __align__(16) char smem[];
    const int t = threadIdx.x, wid = t >> 5, lane = t & 31;
    const int wm = wid & 3, wn = wid >> 2;
    const int n0 = blockIdx.x * 128, m0 = blockIdx.y * 128;
    const int gr = lane >> 2, gc = (lane & 3) * 2;

    float acc[2][8][4];
    #pragma unroll
    for (int i = 0; i < 2; i++)
        #pragma unroll
        for (int j = 0; j < 8; j++)
            #pragma unroll
            for (int q = 0; q < 4; q++) acc[i][j][q] = 0.f;

    // stage filler: buffers 0..3 = Ahi, Alo, Whi, Wlo; 512 x 16B segs each
    auto fill = [&](int slot, int k0) {
        char* sp = smem + slot * (GSLOT * 2);
        #pragma unroll
        for (int i = 0; i < 8; i++) {
            const int buf = i >> 1;
            const int id  = t + (i & 1) * 256;      // 0..511
            const int row = id >> 2, seg = id & 3;
            const bf* s = (buf == 0) ? Ah + (size_t)(m0 + row) * 512
                        : (buf == 1) ? Al + (size_t)(m0 + row) * 512
                        : (buf == 2) ? Wh + (size_t)(n0 + row) * 512
                                     : Wl + (size_t)(n0 + row) * 512;
            cp16(sp + buf * (GBUF * 2) + row * (AST * 2) + seg * 16, s + k0 + seg * 8);
        }
    };

    fill(0, 0);  CP_COMMIT();
    fill(1, 32); CP_COMMIT();

    for (int c = 0; c < 16; c++) {
        if (c + 2 < 16) { fill((c + 2) & 3, (c + 2) * 32); CP_COMMIT(); }
        if (c < 14)      asm volatile("cp.async.wait_group 2;" ::: "memory");
        else if (c == 14) asm volatile("cp.async.wait_group 1;" ::: "memory");
        else              asm volatile("cp.async.wait_group 0;" ::: "memory");
        __syncthreads();

        char* sp  = smem + (c & 3) * (GSLOT * 2);
        bf* Ahi = (bf*)sp;
        bf* Alo = Ahi + GBUF;
        bf* Bhi = Alo + GBUF;
        bf* Blo = Bhi + GBUF;

        #pragma unroll
        for (int kk = 0; kk < 32; kk += 16) {
            uint32_t ah[2][4], al[2][4], bh[8][2], bl[8][2];
            #pragma unroll
            for (int mi = 0; mi < 2; mi++) {
                int r = wm * 32 + mi * 16 + gr;
                ah[mi][0] = *(const uint32_t*)&Ahi[(r    ) * AST + kk + gc];
                ah[mi][1] = *(const uint32_t*)&Ahi[(r + 8) * AST + kk + gc];
                ah[mi][2] = *(const uint32_t*)&Ahi[(r    ) * AST + kk + gc + 8];
                ah[mi][3] = *(const uint32_t*)&Ahi[(r + 8) * AST + kk + gc + 8];
            }
            #pragma unroll
            for (int nj = 0; nj < 8; nj++) {
                int r = wn * 64 + nj * 8 + gr;
                bh[nj][0] = *(const uint32_t*)&Bhi[r * AST + kk + gc];
                bh[nj][1] = *(const uint32_t*)&Bhi[r * AST + kk + gc + 8];
            }
            #pragma unroll
            for (int mi = 0; mi < 2; mi++)
                #pragma unroll
                for (int nj = 0; nj < 8; nj++) mma16816(acc[mi][nj], ah[mi], bh[nj]);

            #pragma unroll
            for (int nj = 0; nj < 8; nj++) {
                int r = wn * 64 + nj * 8 + gr;
                bl[nj][0] = *(const uint32_t*)&Blo[r * AST + kk + gc];
                bl[nj][1] = *(const uint32_t*)&Blo[r * AST + kk + gc + 8];
            }
            #pragma unroll
            for (int mi = 0; mi < 2; mi++)
                #pragma unroll
                for (int nj = 0; nj < 8; nj++) mma16816(acc[mi][nj], ah[mi], bl[nj]);

            #pragma unroll
            for (int mi = 0; mi < 2; mi++) {
                int r = wm * 32 + mi * 16 + gr;
                al[mi][0] = *(const uint32_t*)&Alo[(r    ) * AST + kk + gc];
                al[mi][1] = *(const uint32_t*)&Alo[(r + 8) * AST + kk + gc];
                al[mi][2] = *(const uint32_t*)&Alo[(r    ) * AST + kk + gc + 8];
                al[mi][3] = *(const uint32_t*)&Alo[(r + 8) * AST + kk + gc + 8];
            }
            #pragma unroll
            for (int mi = 0; mi < 2; mi++)
                #pragma unroll
                for (int nj = 0; nj < 8; nj++) mma16816(acc[mi][nj], al[mi], bh[nj]);
        }
    }

    // ---- epilogue ----
    #pragma unroll
    for (int mi = 0; mi < 2; mi++) {
        int r0 = m0 + wm * 32 + mi * 16 + gr;
        #pragma unroll
        for (int nj = 0; nj < 8; nj++) {
            int n = n0 + wn * 64 + nj * 8 + gc;
            float v00 = acc[mi][nj][0] + bv[n];
            float v01 = acc[mi][nj][1] + bv[n + 1];
            float v10 = acc[mi][nj][2] + bv[n];
            float v11 = acc[mi][nj][3] + bv[n + 1];
            if (MODE == 0) {
                int h_ = n >> 6, d_ = n & 63;
                int b0_ = r0 >> 10, s0_ = r0 & 1023;
                int b1_ = (r0 + 8) >> 10, s1_ = (r0 + 8) & 1023;
                size_t p00 = (((size_t)(b0_ * HH + h_) * DKK) + d_) * SS + s0_;
                size_t p01 = (((size_t)(b0_ * HH + h_) * DKK) + d_ + 1) * SS + s0_;
                size_t p10 = (((size_t)(b1_ * HH + h_) * DKK) + d_) * SS + s1_;
                size_t p11 = (((size_t)(b1_ * HH + h_) * DKK) + d_ + 1) * SS + s1_;
                bf hh, ll;
                split1(v00, hh, ll); g_vh[p00] = hh; g_vl[p00] = ll;
                split1(v01, hh, ll); g_vh[p01] = hh; g_vl[p01] = ll;
                split1(v10, hh, ll); g_vh[p10] = hh; g_vl[p10] = ll;
                split1(v11, hh, ll); g_vh[p11] = hh; g_vl[p11] = ll;
            } else {
                Cout[(size_t)r0 * 512 + n]           = v00;
                Cout[(size_t)r0 * 512 + n + 1]       = v01;
                Cout[(size_t)(r0 + 8) * 512 + n]     = v10;
                Cout[(size_t)(r0 + 8) * 512 + n + 1] = v11;
            }
        }
    }
}

// ============== attention: cp.async double-buffered, HMMA PV, no-max softmax ======
// Output now written pre-split (g_xh/g_xl) for the O-projection.
#define PST 72
#define SST 68
#define STAGE_ELEMS (64 * SST)
#define ATTN_SMEM (4 * STAGE_ELEMS * 4 + 4 * 64 * PST * 2 + 256)

__global__ void __launch_bounds__(256, 2) attn3(const float* __restrict__ bias,
                                                const int*   __restrict__ mask,
                                                float*       __restrict__ bias_out)
{
    extern __shared__ __align__(16) char smem[];
    float* stB  = (float*)smem;
    int*   stM  = (int*)(smem + 2 * STAGE_ELEMS * 4);
    bf*    Ph   = (bf*)(smem + 4 * STAGE_ELEMS * 4);
    bf*    Pl   = Ph + 64 * PST;
    bf*    Vh   = Pl + 64 * PST;
    bf*    Vl   = Vh + 64 * PST;
    float* lsum = (float*)(Vl + 64 * PST);

    const int t = threadIdx.x, wid = t >> 5, lane = t & 31;
    const int gr = lane >> 2, gc = (lane & 3) * 2;
    const int wm = wid & 3, wn = wid >> 2;
    const int q0 = blockIdx.x * 64;
    const int h  = blockIdx.y;
    const int b  = blockIdx.z;

    const float* __restrict__ bias_base = bias     + (((size_t)(b * HH + h)) * SS + q0) * SS;
    float*       __restrict__ bout_base = bias_out + (((size_t)(b * HH + h)) * SS + q0) * SS;
    const int*   __restrict__ mask_base = mask     + ((size_t)(b * SS + q0)) * SS;
    const bf*    __restrict__ vh_base   = g_vh + ((size_t)(b * HH + h) * DKK) * SS;
    const bf*    __restrict__ vl_base   = g_vl + ((size_t)(b * HH + h) * DKK) * SS;

    const int prow = t >> 2;
    const int pc0  = (t & 3) * 16;
    const int vrow = t >> 2;
    const int vc0  = (t & 3) * 16;

    float rsum = 0.f;
    float acc[4][4];
    #pragma unroll
    for (int j = 0; j < 4; j++)
        #pragma unroll
        for (int q = 0; q < 4; q++) acc[j][q] = 0.f;

    {
        #pragma unroll
        for (int i = 0; i < 4; i++) {
            int o = t + i * 256; int row = o >> 4, seg = o & 15;
            cp16(&stB[row * SST + seg * 4], &bias_base[(size_t)row * SS + seg * 4]);
            cp16(&stM[row * SST + seg * 4], &mask_base[(size_t)row * SS + seg * 4]);
        }
        CP_COMMIT();
    }

    for (int c = 0; c < 16; c++) {
        const int k0 = c * 64;
        if (c < 15) {
            float* dB = stB + ((c + 1) & 1) * STAGE_ELEMS;
            int*   dM = stM + ((c + 1) & 1) * STAGE_ELEMS;
            #pragma unroll
            for (int i = 0; i < 4; i++) {
                int o = t + i * 256; int row = o >> 4, seg = o & 15;
                cp16(&dB[row * SST + seg * 4], &bias_base[(size_t)row * SS + k0 + 64 + seg * 4]);
                cp16(&dM[row * SST + seg * 4], &mask_base[(size_t)row * SS + k0 + 64 + seg * 4]);
            }
            CP_COMMIT();
            asm volatile("cp.async.wait_group 1;" ::: "memory");
        } else {
            asm volatile("cp.async.wait_group 0;" ::: "memory");
        }
        __syncthreads();

        const float* sB = stB + (c & 1) * STAGE_ELEMS + prow * SST + pc0;
        const int*   sM = stM + (c & 1) * STAGE_ELEMS + prow * SST + pc0;
        float*       bo = bout_base + (size_t)prow * SS + k0 + pc0;
        #pragma unroll
        for (int g = 0; g < 4; g++) {
            float4 b4 = *(const float4*)(sB + g * 4);
            int4   m4 = *(const int4*)(sM + g * 4);
            *(float4*)(bo + g * 4) = b4;
            float p0 = m4.x ? __expf(b4.x) : 0.f;
            float p1 = m4.y ? __expf(b4.y) : 0.f;
            float p2 = m4.z ? __expf(b4.z) : 0.f;
            float p3 = m4.w ? __expf(b4.w) : 0.f;
            rsum += (p0 + p1) + (p2 + p3);
            bf h0,h1,h2,h3,l0,l1,l2,l3;
            split1(p0,h0,l0); split1(p1,h1,l1); split1(p2,h2,l2); split1(p3,h3,l3);
            *(uint2*)&Ph[prow * PST + pc0 + g * 4] = make_uint2(pack_bf(h0,h1), pack_bf(h2,h3));
            *(uint2*)&Pl[prow * PST + pc0 + g * 4] = make_uint2(pack_bf(l0,l1), pack_bf(l2,l3));
        }

        {
            const bf* vh_p = vh_base + (size_t)vrow * SS + k0 + vc0;
            const bf* vl_p = vl_base + (size_t)vrow * SS + k0 + vc0;
            *(uint4*)&Vh[vrow * PST + vc0]     = *(const uint4*)(vh_p);
            *(uint4*)&Vh[vrow * PST + vc0 + 8] = *(const uint4*)(vh_p + 8);
            *(uint4*)&Vl[vrow * PST + vc0]     = *(const uint4*)(vl_p);
            *(uint4*)&Vl[vrow * PST + vc0 + 8] = *(const uint4*)(vl_p + 8);
        }
        __syncthreads();

        const int qb = wm * 16, vb = wn * 32;
        #pragma unroll
        for (int kk = 0; kk < 64; kk += 16) {
            uint32_t ah[4], al[4], bh[4][2], bl[4][2];
            ah[0] = *(const uint32_t*)&Ph[(qb + gr    ) * PST + kk + gc];
            ah[1] = *(const uint32_t*)&Ph[(qb + gr + 8) * PST + kk + gc];
            ah[2] = *(const uint32_t*)&Ph[(qb + gr    ) * PST + kk + gc + 8];
            ah[3] = *(const uint32_t*)&Ph[(qb + gr + 8) * PST + kk + gc + 8];
            #pragma unroll
            for (int nj = 0; nj < 4; nj++) {
                int r = vb + nj * 8 + gr;
                bh[nj][0] = *(const uint32_t*)&Vh[r * PST + kk + gc];
                bh[nj][1] = *(const uint32_t*)&Vh[r * PST + kk + gc + 8];
            }
            #pragma unroll
            for (int nj = 0; nj < 4; nj++) mma16816(acc[nj], ah, bh[nj]);

            #pragma unroll
            for (int nj = 0; nj < 4; nj++) {
                int r = vb + nj * 8 + gr;
                bl[nj][0] = *(const uint32_t*)&Vl[r * PST + kk + gc];
                bl[nj][1] = *(const uint32_t*)&Vl[r * PST + kk + gc + 8];
            }
            #pragma unroll
            for (int nj = 0; nj < 4; nj++) mma16816(acc[nj], ah, bl[nj]);

            al[0] = *(const uint32_t*)&Pl[(qb + gr    ) * PST + kk + gc];
            al[1] = *(const uint32_t*)&Pl[(qb + gr + 8) * PST + kk + gc];
            al[2] = *(const uint32_t*)&Pl[(qb + gr    ) * PST + kk + gc + 8];
            al[3] = *(const uint32_t*)&Pl[(qb + gr + 8) * PST + kk + gc + 8];
            #pragma unroll
            for (int nj = 0; nj < 4; nj++) mma16816(acc[nj], al, bh[nj]);
        }
    }

    rsum += __shfl_xor_sync(0xffffffffu, rsum, 1);
    rsum += __shfl_xor_sync(0xffffffffu, rsum, 2);
    if ((t & 3) == 0) lsum[prow] = rsum;
    __syncthreads();

    const int qb = wm * 16, vb = wn * 32;
    const float inv0 = 1.f / lsum[qb + gr];
    const float inv1 = 1.f / lsum[qb + gr + 8];
    #pragma unroll
    for (int nj = 0; nj < 4; nj++) {
        int dk = vb + nj * 8 + gc;
        size_t o0 = ((size_t)(b * SS + q0 + qb + gr)) * DD + h * 64 + dk;
        size_t o1 = ((size_t)(b * SS + q0 + qb + gr + 8)) * DD + h * 64 + dk;
        bf h0,l0,h1,l1;
        split1(acc[nj][0] * inv0, h0, l0); split1(acc[nj][1] * inv0, h1, l1);
        *(uint32_t*)&g_xh[o0] = pack_bf(h0, h1);
        *(uint32_t*)&g_xl[o0] = pack_bf(l0, l1);
        split1(acc[nj][2] * inv1, h0, l0); split1(acc[nj][3] * inv1, h1, l1);
        *(uint32_t*)&g_xh[o1] = pack_bf(h0, h1);
        *(uint32_t*)&g_xl[o1] = pack_bf(l0, l1);
    }
}

extern "C" void kernel_launch(void* const* d_in, const int* in_sizes, int n_in,
                              void* d_out, int out_size)
{
    // metadata order: query, key, value, bias, mask, W_v, b_v, W_o, b_o
    const float* value = (const float*)d_in[2];
    const float* bias  = (const float*)d_in[3];
    const int*   mask  = (const int*)  d_in[4];
    const float* W_v   = (const float*)d_in[5];
    const float* b_v   = (const float*)d_in[6];
    const float* W_o   = (const float*)d_in[7];
    const float* b_o   = (const float*)d_in[8];

    float* out      = (float*)d_out;                 // [B,S,D]
    float* bias_out = out + (size_t)BB * SS * DD;    // [B,H,S,S]

    cudaFuncSetAttribute(gemm_bf<0>, cudaFuncAttributeMaxDynamicSharedMemorySize, GEMM_SMEM);
    cudaFuncSetAttribute(gemm_bf<1>, cudaFuncAttributeMaxDynamicSharedMemorySize, GEMM_SMEM);
    cudaFuncSetAttribute(attn3, cudaFuncAttributeMaxDynamicSharedMemorySize, ATTN_SMEM);

    bf *p_ah, *p_al, *p_wvh, *p_wvl, *p_woh, *p_wol, *p_xh, *p_xl;
    cudaGetSymbolAddress((void**)&p_ah,  g_ah);
    cudaGetSymbolAddress((void**)&p_al,  g_al);
    cudaGetSymbolAddress((void**)&p_wvh, g_wvh);
    cudaGetSymbolAddress((void**)&p_wvl, g_wvl);
    cudaGetSymbolAddress((void**)&p_woh, g_woh);
    cudaGetSymbolAddress((void**)&p_wol, g_wol);
    cudaGetSymbolAddress((void**)&p_xh,  g_xh);
    cudaGetSymbolAddress((void**)&p_xl,  g_xl);

    // 0) pre-split value, W_v, W_o
    split_prep<<<(N_A4 + 2 * N_W4 + 255) / 256, 256>>>(value, W_v, W_o);

    // 1) V projection -> g_vh/g_vl [b][h][dk][s]
    gemm_bf<0><<<dim3(4, 32), 256, GEMM_SMEM>>>(p_ah, p_al, p_wvh, p_wvl, b_v, nullptr);

    // 2) masked softmax(bias) @ v (+ fused bias copy) -> g_xh/g_xl
    attn3<<<dim3(SS / 64, HH, BB), 256, ATTN_SMEM>>>(bias, mask, bias_out);

    // 3) O projection -> out
    gemm_bf<1><<<dim3(4, 32), 256, GEMM_SMEM>>>(p_xh, p_xl, p_woh, p_wol, b_o, out);
}

// round 8
// speedup vs baseline: 2.4051x; 1.0424x over previous
#include <cuda_runtime.h>
#include <cuda_bf16.h>
#include <stdint.h>
#include <math.h>

#define BB 4
#define HH 8
#define SS 1024
#define DD 512
#define DKK 64

typedef __nv_bfloat16 bf;

// Scratch (allocation-free rule: __device__ globals)
__device__ bf g_vh[BB*HH*DKK*SS];   // V projected, split hi, transposed [b][h][dk][s]
__device__ bf g_vl[BB*HH*DKK*SS];   // V projected, split lo
__device__ bf g_xh[BB*SS*DD];       // attn out, split hi, [b][s][h*64+dk]
__device__ bf g_xl[BB*SS*DD];       // attn out, split lo
__device__ bf g_ah[BB*SS*DD];       // value pre-split hi
__device__ bf g_al[BB*SS*DD];       // value pre-split lo
__device__ bf g_wvh[DD*DD];         // W_v pre-split
__device__ bf g_wvl[DD*DD];
__device__ bf g_woh[DD*DD];         // W_o pre-split
__device__ bf g_wol[DD*DD];

__device__ __forceinline__ uint32_t pack_bf(bf a, bf b) {
    return (uint32_t)__bfloat16_as_ushort(a) | ((uint32_t)__bfloat16_as_ushort(b) << 16);
}
__device__ __forceinline__ void split1(float x, bf& h, bf& l) {
    h = __float2bfloat16(x);
    l = __float2bfloat16(x - __bfloat162float(h));
}

__device__ __forceinline__ void mma16816(float* d, const uint32_t* a, const uint32_t* b) {
    asm volatile(
        "mma.sync.aligned.m16n8k16.row.col.f32.bf16.bf16.f32 "
        "{%0,%1,%2,%3}, {%4,%5,%6,%7}, {%8,%9}, {%0,%1,%2,%3};"
        : "+f"(d[0]), "+f"(d[1]), "+f"(d[2]), "+f"(d[3])
        : "r"(a[0]), "r"(a[1]), "r"(a[2]), "r"(a[3]), "r"(b[0]), "r"(b[1]));
}

__device__ __forceinline__ uint32_t smem_u32(const void* p) {
    uint32_t a;
    asm("{ .reg .u64 t; cvta.to.shared.u64 t, %1; cvt.u32.u64 %0, t; }" : "=r"(a) : "l"(p));
    return a;
}
__device__ __forceinline__ void cp16(void* s, const void* g) {
    uint32_t sa = smem_u32(s);
    asm volatile("cp.async.cg.shared.global [%0], [%1], 16;" :: "r"(sa), "l"(g));
}
#define CP_COMMIT() asm volatile("cp.async.commit_group;" ::: "memory")

// ======================= prep: fp32 -> bf16 hi/lo split =======================
#define N_A4 (BB*SS*DD/4)
#define N_W4 (DD*DD/4)
__global__ void __launch_bounds__(256) split_prep(const float* __restrict__ value,
                                                  const float* __restrict__ Wv,
                                                  const float* __restrict__ Wo)
{
    int i = blockIdx.x * 256 + threadIdx.x;
    const float* src; bf *dh, *dl; int base;
    if (i < N_A4)            { src = value; dh = g_ah;  dl = g_al;  base = i; }
    else if (i < N_A4+N_W4)  { src = Wv;    dh = g_wvh; dl = g_wvl; base = i - N_A4; }
    else                     { src = Wo;    dh = g_woh; dl = g_wol; base = i - N_A4 - N_W4; }
    float4 v = ((const float4*)src)[base];
    bf h0,h1,h2,h3,l0,l1,l2,l3;
    split1(v.x,h0,l0); split1(v.y,h1,l1); split1(v.z,h2,l2); split1(v.w,h3,l3);
    *(uint2*)&dh[(size_t)base*4] = make_uint2(pack_bf(h0,h1), pack_bf(h2,h3));
    *(uint2*)&dl[(size_t)base*4] = make_uint2(pack_bf(l0,l1), pack_bf(l2,l3));
}

// ============== tensor-core GEMM on pre-split bf16, 4-slot cp.async ring =========
#define AST 40
#define GBUF (128 * AST)
#define GSLOT (4 * GBUF)
#define GEMM_SMEM (4 * GSLOT * 2)

template<int MODE>
__global__ void __launch_bounds__(256) gemm_bf(const bf* __restrict__ Ah,
                                               const bf* __restrict__ Al,
                                               const bf* __restrict__ Wh,
                                               const bf* __restrict__ Wl,
                                               const float* __restrict__ bv,
                                               float* __restrict__ Cout)
{
    extern __shared__ __align__(16) char smem[];
    const int t = threadIdx.x, wid = t >> 5, lane = t & 31;
    const int wm = wid & 3, wn = wid >> 2;
    const int n0 = blockIdx.x * 128, m0 = blockIdx.y * 128;
    const int gr = lane >> 2, gc = (lane & 3) * 2;

    float acc[2][8][4];
    #pragma unroll
    for (int i = 0; i < 2; i++)
        #pragma unroll
        for (int j = 0; j < 8; j++)
            #pragma unroll
            for (int q = 0; q < 4; q++) acc[i][j][q] = 0.f;

    auto fill = [&](int slot, int k0) {
        char* sp = smem + slot * (GSLOT * 2);
        #pragma unroll
        for (int i = 0; i < 8; i++) {
            const int buf = i >> 1;
            const int id  = t + (i & 1) * 256;
            const int row = id >> 2, seg = id & 3;
            const bf* s = (buf == 0) ? Ah + (size_t)(m0 + row) * 512
                        : (buf == 1) ? Al + (size_t)(m0 + row) * 512
                        : (buf == 2) ? Wh + (size_t)(n0 + row) * 512
                                     : Wl + (size_t)(n0 + row) * 512;
            cp16(sp + buf * (GBUF * 2) + row * (AST * 2) + seg * 16, s + k0 + seg * 8);
        }
    };

    fill(0, 0);  CP_COMMIT();
    fill(1, 32); CP_COMMIT();

    for (int c = 0; c < 16; c++) {
        if (c + 2 < 16) { fill((c + 2) & 3, (c + 2) * 32); CP_COMMIT(); }
        if (c < 14)      asm volatile("cp.async.wait_group 2;" ::: "memory");
        else if (c == 14) asm volatile("cp.async.wait_group 1;" ::: "memory");
        else              asm volatile("cp.async.wait_group 0;" ::: "memory");
        __syncthreads();

        char* sp  = smem + (c & 3) * (GSLOT * 2);
        bf* Ahi = (bf*)sp;
        bf* Alo = Ahi + GBUF;
        bf* Bhi = Alo + GBUF;
        bf* Blo = Bhi + GBUF;

        #pragma unroll
        for (int kk = 0; kk < 32; kk += 16) {
            uint32_t ah[2][4], al[2][4], bh[8][2], bl[8][2];
            #pragma unroll
            for (int mi = 0; mi < 2; mi++) {
                int r = wm * 32 + mi * 16 + gr;
                ah[mi][0] = *(const uint32_t*)&Ahi[(r    ) * AST + kk + gc];
                ah[mi][1] = *(const uint32_t*)&Ahi[(r + 8) * AST + kk + gc];
                ah[mi][2] = *(const uint32_t*)&Ahi[(r    ) * AST + kk + gc + 8];
                ah[mi][3] = *(const uint32_t*)&Ahi[(r + 8) * AST + kk + gc + 8];
            }
            #pragma unroll
            for (int nj = 0; nj < 8; nj++) {
                int r = wn * 64 + nj * 8 + gr;
                bh[nj][0] = *(const uint32_t*)&Bhi[r * AST + kk + gc];
                bh[nj][1] = *(const uint32_t*)&Bhi[r * AST + kk + gc + 8];
            }
            #pragma unroll
            for (int mi = 0; mi < 2; mi++)
                #pragma unroll
                for (int nj = 0; nj < 8; nj++) mma16816(acc[mi][nj], ah[mi], bh[nj]);

            #pragma unroll
            for (int nj = 0; nj < 8; nj++) {
                int r = wn * 64 + nj * 8 + gr;
                bl[nj][0] = *(const uint32_t*)&Blo[r * AST + kk + gc];
                bl[nj][1] = *(const uint32_t*)&Blo[r * AST + kk + gc + 8];
            }
            #pragma unroll
            for (int mi = 0; mi < 2; mi++)
                #pragma unroll
                for (int nj = 0; nj < 8; nj++) mma16816(acc[mi][nj], ah[mi], bl[nj]);

            #pragma unroll
            for (int mi = 0; mi < 2; mi++) {
                int r = wm * 32 + mi * 16 + gr;
                al[mi][0] = *(const uint32_t*)&Alo[(r    ) * AST + kk + gc];
                al[mi][1] = *(const uint32_t*)&Alo[(r + 8) * AST + kk + gc];
                al[mi][2] = *(const uint32_t*)&Alo[(r    ) * AST + kk + gc + 8];
                al[mi][3] = *(const uint32_t*)&Alo[(r + 8) * AST + kk + gc + 8];
            }
            #pragma unroll
            for (int mi = 0; mi < 2; mi++)
                #pragma unroll
                for (int nj = 0; nj < 8; nj++) mma16816(acc[mi][nj], al[mi], bh[nj]);
        }
    }

    #pragma unroll
    for (int mi = 0; mi < 2; mi++) {
        int r0 = m0 + wm * 32 + mi * 16 + gr;
        #pragma unroll
        for (int nj = 0; nj < 8; nj++) {
            int n = n0 + wn * 64 + nj * 8 + gc;
            float v00 = acc[mi][nj][0] + bv[n];
            float v01 = acc[mi][nj][1] + bv[n + 1];
            float v10 = acc[mi][nj][2] + bv[n];
            float v11 = acc[mi][nj][3] + bv[n + 1];
            if (MODE == 0) {
                int h_ = n >> 6, d_ = n & 63;
                int b0_ = r0 >> 10, s0_ = r0 & 1023;
                int b1_ = (r0 + 8) >> 10, s1_ = (r0 + 8) & 1023;
                size_t p00 = (((size_t)(b0_ * HH + h_) * DKK) + d_) * SS + s0_;
                size_t p01 = (((size_t)(b0_ * HH + h_) * DKK) + d_ + 1) * SS + s0_;
                size_t p10 = (((size_t)(b1_ * HH + h_) * DKK) + d_) * SS + s1_;
                size_t p11 = (((size_t)(b1_ * HH + h_) * DKK) + d_ + 1) * SS + s1_;
                bf hh, ll;
                split1(v00, hh, ll); g_vh[p00] = hh; g_vl[p00] = ll;
                split1(v01, hh, ll); g_vh[p01] = hh; g_vl[p01] = ll;
                split1(v10, hh, ll); g_vh[p10] = hh; g_vl[p10] = ll;
                split1(v11, hh, ll); g_vh[p11] = hh; g_vl[p11] = ll;
            } else {
                Cout[(size_t)r0 * 512 + n]           = v00;
                Cout[(size_t)r0 * 512 + n + 1]       = v01;
                Cout[(size_t)(r0 + 8) * 512 + n]     = v10;
                Cout[(size_t)(r0 + 8) * 512 + n + 1] = v11;
            }
        }
    }
}

// ====== attention v4: m32n32 warp tiles with k-split, early V LDG, cp.async stages ==
// 8 warps = 2(m) x 2(n) x 2(k-half). Cross-k reduction at kernel end via smem.
#define PST 72
#define SST 68
#define STAGE_ELEMS (64 * SST)
#define ATTN_SMEM (4 * STAGE_ELEMS * 4 + 4 * 64 * PST * 2 + 256)

__global__ void __launch_bounds__(256, 2) attn4(const float* __restrict__ bias,
                                                const int*   __restrict__ mask,
                                                float*       __restrict__ bias_out)
{
    extern __shared__ __align__(16) char smem[];
    float* stB  = (float*)smem;
    int*   stM  = (int*)(smem + 2 * STAGE_ELEMS * 4);
    bf*    Ph   = (bf*)(smem + 4 * STAGE_ELEMS * 4);
    bf*    Pl   = Ph + 64 * PST;
    bf*    Vh   = Pl + 64 * PST;
    bf*    Vl   = Vh + 64 * PST;
    float* lsum = (float*)(Vl + 64 * PST);

    const int t = threadIdx.x, wid = t >> 5, lane = t & 31;
    const int gr = lane >> 2, gc = (lane & 3) * 2;
    const int wk = wid >> 2;            // k-half 0/1
    const int wm = (wid >> 1) & 1;      // m-half (32 q rows)
    const int wn = wid & 1;             // n-half (32 dk cols)
    const int q0 = blockIdx.x * 64;
    const int h  = blockIdx.y;
    const int b  = blockIdx.z;

    const float* __restrict__ bias_base = bias     + (((size_t)(b * HH + h)) * SS + q0) * SS;
    float*       __restrict__ bout_base = bias_out + (((size_t)(b * HH + h)) * SS + q0) * SS;
    const int*   __restrict__ mask_base = mask     + ((size_t)(b * SS + q0)) * SS;
    const bf*    __restrict__ vh_base   = g_vh + ((size_t)(b * HH + h) * DKK) * SS;
    const bf*    __restrict__ vl_base   = g_vl + ((size_t)(b * HH + h) * DKK) * SS;

    const int prow = t >> 2;
    const int pc0  = (t & 3) * 16;
    const int vrow = t >> 2;
    const int vc0  = (t & 3) * 16;

    float rsum = 0.f;
    float acc[2][4][4];
    #pragma unroll
    for (int i = 0; i < 2; i++)
        #pragma unroll
        for (int j = 0; j < 4; j++)
            #pragma unroll
            for (int q = 0; q < 4; q++) acc[i][j][q] = 0.f;

    {
        #pragma unroll
        for (int i = 0; i < 4; i++) {
            int o = t + i * 256; int row = o >> 4, seg = o & 15;
            cp16(&stB[row * SST + seg * 4], &bias_base[(size_t)row * SS + seg * 4]);
            cp16(&stM[row * SST + seg * 4], &mask_base[(size_t)row * SS + seg * 4]);
        }
        CP_COMMIT();
    }

    for (int c = 0; c < 16; c++) {
        const int k0 = c * 64;
        if (c < 15) {
            float* dB = stB + ((c + 1) & 1) * STAGE_ELEMS;
            int*   dM = stM + ((c + 1) & 1) * STAGE_ELEMS;
            #pragma unroll
            for (int i = 0; i < 4; i++) {
                int o = t + i * 256; int row = o >> 4, seg = o & 15;
                cp16(&dB[row * SST + seg * 4], &bias_base[(size_t)row * SS + k0 + 64 + seg * 4]);
                cp16(&dM[row * SST + seg * 4], &mask_base[(size_t)row * SS + k0 + 64 + seg * 4]);
            }
            CP_COMMIT();
            asm volatile("cp.async.wait_group 1;" ::: "memory");
        } else {
            asm volatile("cp.async.wait_group 0;" ::: "memory");
        }
        __syncthreads();   // stage ready; prev MMA done (P/V safe to overwrite)

        // ---- issue V LDGs early: latency hidden under P-gen ----
        uint4 vh0, vh1, vl0, vl1;
        {
            const bf* vh_p = vh_base + (size_t)vrow * SS + k0 + vc0;
            const bf* vl_p = vl_base + (size_t)vrow * SS + k0 + vc0;
            vh0 = *(const uint4*)(vh_p);
            vh1 = *(const uint4*)(vh_p + 8);
            vl0 = *(const uint4*)(vl_p);
            vl1 = *(const uint4*)(vl_p + 8);
        }

        // ---- P gen from staged smem (+ bias copy-out) ----
        const float* sB = stB + (c & 1) * STAGE_ELEMS + prow * SST + pc0;
        const int*   sM = stM + (c & 1) * STAGE_ELEMS + prow * SST + pc0;
        float*       bo = bout_base + (size_t)prow * SS + k0 + pc0;
        #pragma unroll
        for (int g = 0; g < 4; g++) {
            float4 b4 = *(const float4*)(sB + g * 4);
            int4   m4 = *(const int4*)(sM + g * 4);
            *(float4*)(bo + g * 4) = b4;
            float p0 = m4.x ? __expf(b4.x) : 0.f;
            float p1 = m4.y ? __expf(b4.y) : 0.f;
            float p2 = m4.z ? __expf(b4.z) : 0.f;
            float p3 = m4.w ? __expf(b4.w) : 0.f;
            rsum += (p0 + p1) + (p2 + p3);
            bf h0,h1,h2,h3,l0,l1,l2,l3;
            split1(p0,h0,l0); split1(p1,h1,l1); split1(p2,h2,l2); split1(p3,h3,l3);
            *(uint2*)&Ph[prow * PST + pc0 + g * 4] = make_uint2(pack_bf(h0,h1), pack_bf(h2,h3));
            *(uint2*)&Pl[prow * PST + pc0 + g * 4] = make_uint2(pack_bf(l0,l1), pack_bf(l2,l3));
        }

        // ---- store V (arrived by now) ----
        *(uint4*)&Vh[vrow * PST + vc0]     = vh0;
        *(uint4*)&Vh[vrow * PST + vc0 + 8] = vh1;
        *(uint4*)&Vl[vrow * PST + vc0]     = vl0;
        *(uint4*)&Vl[vrow * PST + vc0 + 8] = vl1;
        __syncthreads();

        // ---- MMA: warp tile m32 x n32 x k32(half), 2 k16 steps, 3 passes ----
        const int qb = wm * 32, vb = wn * 32, kb = wk * 32;
        #pragma unroll
        for (int kks = 0; kks < 32; kks += 16) {
            const int kk = kb + kks;
            uint32_t ah[2][4], al[2][4], bh[4][2], bl[4][2];
            #pragma unroll
            for (int mi = 0; mi < 2; mi++) {
                int r = qb + mi * 16 + gr;
                ah[mi][0] = *(const uint32_t*)&Ph[(r    ) * PST + kk + gc];
                ah[mi][1] = *(const uint32_t*)&Ph[(r + 8) * PST + kk + gc];
                ah[mi][2] = *(const uint32_t*)&Ph[(r    ) * PST + kk + gc + 8];
                ah[mi][3] = *(const uint32_t*)&Ph[(r + 8) * PST + kk + gc + 8];
            }
            #pragma unroll
            for (int nj = 0; nj < 4; nj++) {
                int r = vb + nj * 8 + gr;
                bh[nj][0] = *(const uint32_t*)&Vh[r * PST + kk + gc];
                bh[nj][1] = *(const uint32_t*)&Vh[r * PST + kk + gc + 8];
            }
            #pragma unroll
            for (int mi = 0; mi < 2; mi++)
                #pragma unroll
                for (int nj = 0; nj < 4; nj++) mma16816(acc[mi][nj], ah[mi], bh[nj]);

            #pragma unroll
            for (int nj = 0; nj < 4; nj++) {
                int r = vb + nj * 8 + gr;
                bl[nj][0] = *(const uint32_t*)&Vl[r * PST + kk + gc];
                bl[nj][1] = *(const uint32_t*)&Vl[r * PST + kk + gc + 8];
            }
            #pragma unroll
            for (int mi = 0; mi < 2; mi++)
                #pragma unroll
                for (int nj = 0; nj < 4; nj++) mma16816(acc[mi][nj], ah[mi], bl[nj]);

            #pragma unroll
            for (int mi = 0; mi < 2; mi++) {
                int r = qb + mi * 16 + gr;
                al[mi][0] = *(const uint32_t*)&Pl[(r    ) * PST + kk + gc];
                al[mi][1] = *(const uint32_t*)&Pl[(r + 8) * PST + kk + gc];
                al[mi][2] = *(const uint32_t*)&Pl[(r    ) * PST + kk + gc + 8];
                al[mi][3] = *(const uint32_t*)&Pl[(r + 8) * PST + kk + gc + 8];
            }
            #pragma unroll
            for (int mi = 0; mi < 2; mi++)
                #pragma unroll
                for (int nj = 0; nj < 4; nj++) mma16816(acc[mi][nj], al[mi], bh[nj]);
        }
    }

    // ---- rowsum combine: 4 threads (t&3) share row prow ----
    rsum += __shfl_xor_sync(0xffffffffu, rsum, 1);
    rsum += __shfl_xor_sync(0xffffffffu, rsum, 2);
    if ((t & 3) == 0) lsum[prow] = rsum;

    // ---- cross-k reduction: wk==1 warps dump acc; wk==0 warps add ----
    float* red = stB;   // reuse stage buffer; stride 36 floats avoids conflicts
    const int w4 = wid & 3;
    __syncthreads();
    if (wk == 1) {
        float* dst = red + (w4 * 32 + lane) * 36;
        #pragma unroll
        for (int mi = 0; mi < 2; mi++)
            #pragma unroll
            for (int nj = 0; nj < 4; nj++)
                *(float4*)&dst[(mi * 4 + nj) * 4] = *(float4*)acc[mi][nj];
    }
    __syncthreads();
    if (wk == 0) {
        const float* src = red + (w4 * 32 + lane) * 36;
        #pragma unroll
        for (int mi = 0; mi < 2; mi++)
            #pragma unroll
            for (int nj = 0; nj < 4; nj++) {
                float4 v = *(const float4*)&src[(mi * 4 + nj) * 4];
                acc[mi][nj][0] += v.x; acc[mi][nj][1] += v.y;
                acc[mi][nj][2] += v.z; acc[mi][nj][3] += v.w;
            }

        const int qb = wm * 32, vb = wn * 32;
        #pragma unroll
        for (int mi = 0; mi < 2; mi++) {
            const int r0 = qb + mi * 16 + gr;
            const float inv0 = 1.f / lsum[r0];
            const float inv1 = 1.f / lsum[r0 + 8];
            #pragma unroll
            for (int nj = 0; nj < 4; nj++) {
                int dk = vb + nj * 8 + gc;
                size_t o0 = ((size_t)(b * SS + q0 + r0)) * DD + h * 64 + dk;
                size_t o1 = ((size_t)(b * SS + q0 + r0 + 8)) * DD + h * 64 + dk;
                bf h0,l0,h1,l1;
                split1(acc[mi][nj][0] * inv0, h0, l0); split1(acc[mi][nj][1] * inv0, h1, l1);
                *(uint32_t*)&g_xh[o0] = pack_bf(h0, h1);
                *(uint32_t*)&g_xl[o0] = pack_bf(l0, l1);
                split1(acc[mi][nj][2] * inv1, h0, l0); split1(acc[mi][nj][3] * inv1, h1, l1);
                *(uint32_t*)&g_xh[o1] = pack_bf(h0, h1);
                *(uint32_t*)&g_xl[o1] = pack_bf(l0, l1);
            }
        }
    }
}

extern "C" void kernel_launch(void* const* d_in, const int* in_sizes, int n_in,
                              void* d_out, int out_size)
{
    // metadata order: query, key, value, bias, mask, W_v, b_v, W_o, b_o
    const float* value = (const float*)d_in[2];
    const float* bias  = (const float*)d_in[3];
    const int*   mask  = (const int*)  d_in[4];
    const float* W_v   = (const float*)d_in[5];
    const float* b_v   = (const float*)d_in[6];
    const float* W_o   = (const float*)d_in[7];
    const float* b_o   = (const float*)d_in[8];

    float* out      = (float*)d_out;                 // [B,S,D]
    float* bias_out = out + (size_t)BB * SS * DD;    // [B,H,S,S]

    cudaFuncSetAttribute(gemm_bf<0>, cudaFuncAttributeMaxDynamicSharedMemorySize, GEMM_SMEM);
    cudaFuncSetAttribute(gemm_bf<1>, cudaFuncAttributeMaxDynamicSharedMemorySize, GEMM_SMEM);
    cudaFuncSetAttribute(attn4, cudaFuncAttributeMaxDynamicSharedMemorySize, ATTN_SMEM);

    bf *p_ah, *p_al, *p_wvh, *p_wvl, *p_woh, *p_wol, *p_xh, *p_xl;
    cudaGetSymbolAddress((void**)&p_ah,  g_ah);
    cudaGetSymbolAddress((void**)&p_al,  g_al);
    cudaGetSymbolAddress((void**)&p_wvh, g_wvh);
    cudaGetSymbolAddress((void**)&p_wvl, g_wvl);
    cudaGetSymbolAddress((void**)&p_woh, g_woh);
    cudaGetSymbolAddress((void**)&p_wol, g_wol);
    cudaGetSymbolAddress((void**)&p_xh,  g_xh);
    cudaGetSymbolAddress((void**)&p_xl,  g_xl);

    // 0) pre-split value, W_v, W_o
    split_prep<<<(N_A4 + 2 * N_W4 + 255) / 256, 256>>>(value, W_v, W_o);

    // 1) V projection -> g_vh/g_vl [b][h][dk][s]
    gemm_bf<0><<<dim3(4, 32), 256, GEMM_SMEM>>>(p_ah, p_al, p_wvh, p_wvl, b_v, nullptr);

    // 2) masked softmax(bias) @ v (+ fused bias copy) -> g_xh/g_xl
    attn4<<<dim3(SS / 64, HH, BB), 256, ATTN_SMEM>>>(bias, mask, bias_out);

    // 3) O projection -> out
    gemm_bf<1><<<dim3(4, 32), 256, GEMM_SMEM>>>(p_xh, p_xl, p_woh, p_wol, b_o, out);
}